// round 8
// baseline (speedup 1.0000x reference)
#include <cuda_runtime.h>
#include <math.h>
#include <stdint.h>

#define BB 64
#define SS 512
#define DD 768
#define HH 4
#define DHH 192
#define PP 8
#define NPER 9
#define NN 576
#define E0 4096
#define NE 8768       // 2*E0 + NN self loops
#define KTILES 24     // 768 / 32
#define GRID 148
#define NTILE 108     // 9 m-tiles * 12 n-tiles

// dynamic smem layout (bytes):
//  As: 3 stages * 64 rows * 36 floats * 4  = 27648   (row stride 144 B)
//  Bs: 3 stages * 32 rows * 72 floats * 4  = 27648   (base 27648, row stride 288 B)
//  Ws: 3 stages * 8 slots * 32 floats * 4  =  3072   (base 55296)
#define SMEM_BYTES 58368
#define A_OFF(s,m,q4) ((s)*9216 + (m)*144 + (q4)*16)
#define B_OFF(s,k,q4) (27648 + (s)*9216 + (k)*288 + (q4)*16)
#define W_OFF(s,p,q4) (55296 + (s)*1024 + (p)*128 + (q4)*16)

// ---------------- device scratch ----------------
__device__ float g_x[NN * DD];
__device__ float g_h[NN * DD];
__device__ float g_as[NN * HH];
__device__ float g_ad[NN * HH];
__device__ float g_was[5 * 8 * DD];
__device__ int   g_deg[NN];
__device__ int   g_off[NN + 1];
__device__ int   g_cur[NN];
__device__ int   g_srcv[NE];

// grid barrier state
__device__ unsigned g_arr = 0;
__device__ volatile unsigned g_gen = 0;

__device__ __forceinline__ void gsync() {
    __syncthreads();
    if (threadIdx.x == 0) {
        unsigned old = g_gen;
        __threadfence();
        if (atomicAdd(&g_arr, 1u) == GRID - 1) {
            g_arr = 0;
            __threadfence();
            g_gen = old + 1;
        } else {
            while (g_gen == old) { }
            __threadfence();
        }
    }
    __syncthreads();
}

__device__ __forceinline__ void edge_sd(int e, const int* __restrict__ ei, int& s, int& d) {
    if (e < E0)          { s = ei[e];      d = ei[E0 + e]; }
    else if (e < 2 * E0) { s = ei[e];      d = ei[e - E0]; }
    else                 { s = e - 2 * E0; d = e - 2 * E0; }
}

__device__ __forceinline__ void cpa16(uint32_t saddr, const void* gptr) {
    asm volatile("cp.async.cg.shared.global [%0], [%1], 16;\n" :: "r"(saddr), "l"(gptr));
}
__device__ __forceinline__ void cpa_commit() { asm volatile("cp.async.commit_group;\n"); }

// =================== fused GNN kernel ===================
__global__ __launch_bounds__(256, 1) void gnn_fused(
    const int* __restrict__ src,
    const int* __restrict__ sstart,
    const int* __restrict__ send,
    const int* __restrict__ ei,
    const float* __restrict__ wt,
    const float* __restrict__ W_gat,
    const float* __restrict__ a_s_g,
    const float* __restrict__ a_d_g,
    const float* __restrict__ b_gat)
{
    extern __shared__ __align__(16) char smem_raw[];
    float* smf = (float*)smem_raw;
    const int bid = blockIdx.x;
    const int tid = threadIdx.x;
    uint32_t smem_base = (uint32_t)__cvta_generic_to_shared(smem_raw);

    // ---------- phase 0: build nodes + zero deg + prep_was ----------
    for (int node = bid; node < NN; node += GRID) {
        if (tid == 0) g_deg[node] = 0;
        if (tid < 192) {
            int b = node / NPER, p = node % NPER;
            int j0 = 4 * tid;
            float4 v = make_float4(0.f, 0.f, 0.f, 0.f);
            if (p == 0) {
                v = *(const float4*)&wt[(size_t)src[b * SS] * DD + j0];
            } else {
                int st = sstart[b * PP + (p - 1)];
                int en = send[b * PP + (p - 1)];
                for (int s = st; s <= en; s++) {
                    float4 w = *(const float4*)&wt[(size_t)src[b * SS + s] * DD + j0];
                    v.x += w.x; v.y += w.y; v.z += w.z; v.w += w.w;
                }
            }
            *(float4*)&g_x[node * DD + j0] = v;
        }
    }
    // prep_was: 5 layers * 768 k * 4 heads = 15360 items
    for (int idx = bid * 256 + tid; idx < 5 * DD * 4; idx += GRID * 256) {
        int sp = idx & 3;
        int k = (idx >> 2) % DD;
        int l = idx / (DD * 4);
        const float* wseg = W_gat + (size_t)l * DD * DD + (size_t)k * DD + sp * DHH;
        const float* av = a_s_g + l * DD + sp * DHH;
        const float* bv = a_d_g + l * DD + sp * DHH;
        float s0 = 0.f, s1 = 0.f;
#pragma unroll 8
        for (int i = 0; i < DHH; i += 4) {
            float4 w = *(const float4*)&wseg[i];
            float4 a = *(const float4*)&av[i];
            float4 b = *(const float4*)&bv[i];
            s0 += w.x * a.x + w.y * a.y + w.z * a.z + w.w * a.w;
            s1 += w.x * b.x + w.y * b.y + w.z * b.z + w.w * b.w;
        }
        g_was[(l * 8 + sp) * DD + k]     = s0;
        g_was[(l * 8 + sp + 4) * DD + k] = s1;
    }
    gsync();

    // ---------- phase 1: csr count ----------
    {
        int e = bid * 256 + tid;
        if (e < NE) { int s, d; edge_sd(e, ei, s, d); atomicAdd(&g_deg[d], 1); }
    }
    gsync();

    // ---------- phase 2: scan (block 0) ----------
    if (bid == 0) {
        int* part = (int*)smem_raw;
        int* vals = part + 256;
        if (tid < 192) {
            int s = 0;
#pragma unroll
            for (int j = 0; j < 3; j++) {
                int v = __ldcg(&g_deg[tid * 3 + j]);
                vals[tid * 3 + j] = v; s += v;
            }
            part[tid] = s;
        }
        __syncthreads();
        for (int off = 1; off < 192; off <<= 1) {
            int v = (tid < 192 && tid >= off) ? part[tid - off] : 0;
            __syncthreads();
            if (tid < 192) part[tid] += v;
            __syncthreads();
        }
        if (tid < 192) {
            int run = part[tid] - (vals[tid * 3] + vals[tid * 3 + 1] + vals[tid * 3 + 2]);
#pragma unroll
            for (int j = 0; j < 3; j++) {
                g_off[tid * 3 + j] = run;
                g_cur[tid * 3 + j] = run;
                run += vals[tid * 3 + j];
            }
            if (tid == 191) g_off[NN] = run;
        }
    }
    gsync();

    // ---------- phase 3: csr fill ----------
    {
        int e = bid * 256 + tid;
        if (e < NE) {
            int s, d; edge_sd(e, ei, s, d);
            int pos = atomicAdd(&g_cur[d], 1);
            g_srcv[pos] = s;
        }
    }
    // no barrier needed here: post-GEMM barrier of layer 0 orders fill before aggregate

    // GEMM thread mapping (constant across layers)
    const int lane = tid & 31, wid = tid >> 5;
    const int wm = wid >> 2, wn = wid & 3;
    const int g = lane >> 2, tig = lane & 3;
    const int lrow = lane & 15;
    const int lkoff = (lane < 16) ? 0 : 4;
    const int am1 = tid >> 3, aq = tid & 7;
    const int bk1 = tid >> 4, bq = tid & 15;
    const int wslot = tid >> 3, wq = tid & 7;
    const int sr = tid & 63, sp = tid >> 6;

    for (int l = 0; l < 5; l++) {
        const float* Wl = W_gat + (size_t)l * DD * DD;
        const float* wasl = g_was + (size_t)l * 8 * DD;

        // ---------- GEMM: g_h = g_x @ Wl (+ alpha sidecar on bn==0 tiles) ----------
        if (bid < NTILE) {
            const int bm = (bid / 12) * 64, bn = (bid % 12) * 64;
            const bool side = ((bid % 12) == 0);

            float d[2][2][4];
#pragma unroll
            for (int i = 0; i < 2; i++)
#pragma unroll
                for (int j = 0; j < 2; j++)
#pragma unroll
                    for (int q = 0; q < 4; q++) d[i][j][q] = 0.f;
            float sa0 = 0.f, sa1 = 0.f;

#define LOAD_TILE(st, k0)                                                         \
    do {                                                                          \
        cpa16(smem_base + A_OFF(st, am1, aq),    &g_x[(bm + am1) * DD + (k0) + aq * 4]);       \
        cpa16(smem_base + A_OFF(st, am1 + 32, aq), &g_x[(bm + am1 + 32) * DD + (k0) + aq * 4]); \
        cpa16(smem_base + B_OFF(st, bk1, bq),    &Wl[(size_t)((k0) + bk1) * DD + bn + bq * 4]); \
        cpa16(smem_base + B_OFF(st, bk1 + 16, bq), &Wl[(size_t)((k0) + bk1 + 16) * DD + bn + bq * 4]); \
        if (side && tid < 64)                                                     \
            cpa16(smem_base + W_OFF(st, wslot, wq), &wasl[wslot * DD + (k0) + wq * 4]); \
        cpa_commit();                                                             \
    } while (0)

            LOAD_TILE(0, 0);
            LOAD_TILE(1, 32);

#pragma unroll 1
            for (int t = 0; t < KTILES; t++) {
                if (t < KTILES - 1) asm volatile("cp.async.wait_group 1;\n");
                else                asm volatile("cp.async.wait_group 0;\n");
                __syncthreads();
                if (t + 2 < KTILES) {
                    int st2 = (t + 2) % 3;
                    LOAD_TILE(st2, (t + 2) * 32);
                }
                const int st3 = t % 3;
                uint32_t abase = smem_base + st3 * 9216 + (wm * 32 + lrow) * 144 + lkoff * 4;
#pragma unroll
                for (int ks = 0; ks < 4; ks++) {
                    const int kk = ks * 8;
                    uint32_t a[2][4], b[2][2];
#pragma unroll
                    for (int mt = 0; mt < 2; mt++) {
                        uint32_t addr = abase + mt * (16 * 144) + ks * 32;
                        asm volatile(
                            "ldmatrix.sync.aligned.m8n8.x4.shared.b16 {%0,%1,%2,%3}, [%4];\n"
                            : "=r"(a[mt][0]), "=r"(a[mt][1]), "=r"(a[mt][2]), "=r"(a[mt][3])
                            : "r"(addr));
                    }
#pragma unroll
                    for (int nt = 0; nt < 2; nt++) {
                        int c0 = wn * 16 + nt * 8 + g;
                        b[nt][0] = __float_as_uint(smf[6912 + st3 * 2304 + (kk + tig) * 72 + c0]);
                        b[nt][1] = __float_as_uint(smf[6912 + st3 * 2304 + (kk + tig + 4) * 72 + c0]);
                    }
#pragma unroll
                    for (int mt = 0; mt < 2; mt++)
#pragma unroll
                        for (int nt = 0; nt < 2; nt++) {
                            asm volatile(
                                "mma.sync.aligned.m16n8k8.row.col.f32.tf32.tf32.f32 "
                                "{%0,%1,%2,%3}, {%4,%5,%6,%7}, {%8,%9}, {%0,%1,%2,%3};\n"
                                : "+f"(d[mt][nt][0]), "+f"(d[mt][nt][1]),
                                  "+f"(d[mt][nt][2]), "+f"(d[mt][nt][3])
                                : "r"(a[mt][0]), "r"(a[mt][1]), "r"(a[mt][2]), "r"(a[mt][3]),
                                  "r"(b[nt][0]), "r"(b[nt][1]));
                        }
                }
                if (side) {
#pragma unroll
                    for (int q = 0; q < 8; q++) {
                        float4 xv = *(const float4*)(smem_raw + A_OFF(st3, sr, q));
                        float4 w0 = *(const float4*)(smem_raw + W_OFF(st3, sp, q));
                        float4 w1 = *(const float4*)(smem_raw + W_OFF(st3, sp + 4, q));
                        sa0 += xv.x * w0.x + xv.y * w0.y + xv.z * w0.z + xv.w * w0.w;
                        sa1 += xv.x * w1.x + xv.y * w1.y + xv.z * w1.z + xv.w * w1.w;
                    }
                }
            }
#undef LOAD_TILE

#pragma unroll
            for (int mt = 0; mt < 2; mt++)
#pragma unroll
                for (int nt = 0; nt < 2; nt++) {
                    int row = bm + wm * 32 + mt * 16 + g;
                    int col = bn + wn * 16 + nt * 8 + 2 * tig;
                    *(float2*)&g_h[(size_t)row * DD + col] =
                        make_float2(d[mt][nt][0], d[mt][nt][1]);
                    *(float2*)&g_h[(size_t)(row + 8) * DD + col] =
                        make_float2(d[mt][nt][2], d[mt][nt][3]);
                }
            if (side) {
                int r = bm + sr;
                g_as[r * HH + sp] = sa0;
                g_ad[r * HH + sp] = sa1;
            }
        }
        gsync();

        // ---------- aggregate: online softmax + gather + bias + GELU ----------
        {
            float* s_as = smf;            // 2304 floats
            float* s_ad = smf + NN * HH;  // 2304 floats
            for (int i = tid; i < NN * HH; i += 256) {
                s_as[i] = __ldcg(&g_as[i]);
                s_ad[i] = __ldcg(&g_ad[i]);
            }
            __syncthreads();
            if (tid < 192) {
                const float* bl = b_gat + l * DD;
                int j0 = 4 * tid;
                int h = tid / 48;
                float4 b4 = *(const float4*)&bl[j0];
                for (int d = bid; d < NN; d += GRID) {
                    int beg = g_off[d], end = g_off[d + 1];
                    float ah = s_ad[d * HH + h];
                    float m = -3.0e38f, den = 0.f;
                    float4 acc = make_float4(0.f, 0.f, 0.f, 0.f);
#pragma unroll 2
                    for (int e = beg; e < end; e++) {
                        int s = g_srcv[e];
                        float lg = s_as[s * HH + h] + ah;
                        lg = (lg > 0.f) ? lg : 0.2f * lg;
                        float nm = fmaxf(m, lg);
                        float sc = __expf(m - nm);
                        float p  = __expf(lg - nm);
                        float4 hv = __ldcg((const float4*)&g_h[(size_t)s * DD + j0]);
                        den = den * sc + p;
                        acc.x = acc.x * sc + p * hv.x;
                        acc.y = acc.y * sc + p * hv.y;
                        acc.z = acc.z * sc + p * hv.z;
                        acc.w = acc.w * sc + p * hv.w;
                        m = nm;
                    }
                    float inv = 1.0f / den;
                    float o0 = acc.x * inv + b4.x;
                    float o1 = acc.y * inv + b4.y;
                    float o2 = acc.z * inv + b4.z;
                    float o3 = acc.w * inv + b4.w;
                    float4 r;
                    r.x = 0.5f * o0 * (1.0f + erff(o0 * 0.70710678118654752f));
                    r.y = 0.5f * o1 * (1.0f + erff(o1 * 0.70710678118654752f));
                    r.z = 0.5f * o2 * (1.0f + erff(o2 * 0.70710678118654752f));
                    r.w = 0.5f * o3 * (1.0f + erff(o3 * 0.70710678118654752f));
                    *(float4*)&g_x[(size_t)d * DD + j0] = r;
                }
            }
        }
        if (l < 4) gsync();
    }
}

// =================== final embedding sum + LayerNorm ===================
__global__ void final_ln(const int* __restrict__ src, const int* __restrict__ seg,
                         const int* __restrict__ typ, const int* __restrict__ pos,
                         const float* __restrict__ wt, const float* __restrict__ pt,
                         const float* __restrict__ st, const float* __restrict__ tt,
                         const float* __restrict__ gamma, const float* __restrict__ beta,
                         float* __restrict__ out) {
    int row = blockIdx.x * 8 + (threadIdx.x >> 5);
    int lane = threadIdx.x & 31;
    int b = row / SS, s = row % SS;
    const float* wrow = (s == 0) ? &g_x[(size_t)(b * NPER) * DD]
                                 : &wt[(size_t)src[row] * DD];
    const float* prow = &pt[(size_t)pos[row] * DD];
    const float* srow = &st[(size_t)seg[row] * DD];
    const float* trow = &tt[(size_t)typ[row] * DD];
    float4 v[6];
    float sum = 0.0f, sq = 0.0f;
#pragma unroll
    for (int i = 0; i < 6; i++) {
        int f = (lane + i * 32) * 4;
        float4 w = *(const float4*)&wrow[f];
        float4 p = *(const float4*)&prow[f];
        float4 sg = *(const float4*)&srow[f];
        float4 ty = *(const float4*)&trow[f];
        float4 e = make_float4(w.x + p.x + sg.x + ty.x, w.y + p.y + sg.y + ty.y,
                               w.z + p.z + sg.z + ty.z, w.w + p.w + sg.w + ty.w);
        v[i] = e;
        sum += e.x + e.y + e.z + e.w;
        sq += e.x * e.x + e.y * e.y + e.z * e.z + e.w * e.w;
    }
#pragma unroll
    for (int o = 16; o; o >>= 1) {
        sum += __shfl_xor_sync(0xffffffffu, sum, o);
        sq  += __shfl_xor_sync(0xffffffffu, sq, o);
    }
    float mu  = sum * (1.0f / DD);
    float var = sq * (1.0f / DD) - mu * mu;
    float inv = rsqrtf(var + 1e-6f);
#pragma unroll
    for (int i = 0; i < 6; i++) {
        int f = (lane + i * 32) * 4;
        float4 g4 = *(const float4*)&gamma[f];
        float4 b4 = *(const float4*)&beta[f];
        float4 r;
        r.x = g4.x * (v[i].x - mu) * inv + b4.x;
        r.y = g4.y * (v[i].y - mu) * inv + b4.y;
        r.z = g4.z * (v[i].z - mu) * inv + b4.z;
        r.w = g4.w * (v[i].w - mu) * inv + b4.w;
        *(float4*)&out[(size_t)row * DD + f] = r;
    }
}

extern "C" void kernel_launch(void* const* d_in, const int* in_sizes, int n_in,
                              void* d_out, int out_size) {
    const int*   src        = (const int*)d_in[0];
    const int*   seg        = (const int*)d_in[1];
    const int*   type_ids   = (const int*)d_in[2];
    const int*   pos        = (const int*)d_in[3];
    const int*   span_start = (const int*)d_in[4];
    const int*   span_end   = (const int*)d_in[5];
    const int*   edge_idx   = (const int*)d_in[6];
    const float* word_table = (const float*)d_in[7];
    const float* pos_table  = (const float*)d_in[8];
    const float* seg_table  = (const float*)d_in[9];
    const float* type_table = (const float*)d_in[10];
    const float* gamma      = (const float*)d_in[11];
    const float* beta       = (const float*)d_in[12];
    const float* W_gat      = (const float*)d_in[13];
    const float* a_src      = (const float*)d_in[14];
    const float* a_dst      = (const float*)d_in[15];
    const float* b_gat      = (const float*)d_in[16];
    float* out = (float*)d_out;

    cudaFuncSetAttribute(gnn_fused, cudaFuncAttributeMaxDynamicSharedMemorySize, SMEM_BYTES);

    gnn_fused<<<GRID, 256, SMEM_BYTES>>>(src, span_start, span_end, edge_idx,
                                         word_table, W_gat, a_src, a_dst, b_gat);

    final_ln<<<(BB * SS) / 8, 256>>>(src, seg, type_ids, pos,
                                     word_table, pos_table, seg_table, type_table,
                                     gamma, beta, out);
}

// round 9
// speedup vs baseline: 1.2153x; 1.2153x over previous
#include <cuda_runtime.h>
#include <math.h>
#include <stdint.h>

#define BB 64
#define SS 512
#define DD 768
#define HH 4
#define DHH 192
#define PP 8
#define NPER 9
#define NN 576
#define E0 4096
#define NE 8768       // 2*E0 + NN self loops
#define KTILES 24     // 768 / 32
#define AP 36
#define BP 72

// ---------------- device scratch ----------------
__device__ float g_x[NN * DD];
__device__ float g_h[NN * DD];
__device__ float g_as[NN * HH];
__device__ float g_ad[NN * HH];
__device__ float g_was[5 * 8 * DD];     // per layer: 0-3 = W@a_src heads, 4-7 = W@a_dst
__device__ int   g_deg[NN];
__device__ int   g_off[NN + 1];
__device__ int   g_cur[NN];
__device__ int   g_srcv[NE];

__device__ __forceinline__ void edge_sd(int e, const int* __restrict__ ei, int& s, int& d) {
    if (e < E0)          { s = ei[e];      d = ei[E0 + e]; }
    else if (e < 2 * E0) { s = ei[e];      d = ei[e - E0]; }
    else                 { s = e - 2 * E0; d = e - 2 * E0; }
}

__device__ __forceinline__ void cpa16(uint32_t saddr, const void* gptr) {
    asm volatile("cp.async.cg.shared.global [%0], [%1], 16;\n" :: "r"(saddr), "l"(gptr));
}
__device__ __forceinline__ void cpa_commit() { asm volatile("cp.async.commit_group;\n"); }

// ---------------- 1. node assembly (+deg zero) ----------------
__global__ void build_nodes(const int* __restrict__ src,
                            const int* __restrict__ sstart,
                            const int* __restrict__ send,
                            const float* __restrict__ wt) {
    int node = blockIdx.x;
    if (threadIdx.x == 0) g_deg[node] = 0;
    int b = node / NPER, p = node % NPER;
    int j0 = 4 * threadIdx.x;
    float4 v = make_float4(0.f, 0.f, 0.f, 0.f);
    if (p == 0) {
        v = *(const float4*)&wt[(size_t)src[b * SS] * DD + j0];
    } else {
        int st = sstart[b * PP + (p - 1)];
        int en = send[b * PP + (p - 1)];
        for (int s = st; s <= en; s++) {
            float4 w = *(const float4*)&wt[(size_t)src[b * SS + s] * DD + j0];
            v.x += w.x; v.y += w.y; v.z += w.z; v.w += w.w;
        }
    }
    *(float4*)&g_x[node * DD + j0] = v;
}

// ---------------- 2. CSR build ----------------
__global__ void csr_count(const int* __restrict__ ei) {
    int e = blockIdx.x * blockDim.x + threadIdx.x;
    if (e >= NE) return;
    int s, d; edge_sd(e, ei, s, d);
    atomicAdd(&g_deg[d], 1);
}
__global__ void csr_scan() {
    __shared__ int sh[1024];
    int t = threadIdx.x;
    int dv = (t < NN) ? g_deg[t] : 0;
    sh[t] = dv;
    __syncthreads();
    for (int off = 1; off < 1024; off <<= 1) {
        int v = (t >= off) ? sh[t - off] : 0;
        __syncthreads();
        sh[t] += v;
        __syncthreads();
    }
    if (t < NN) {
        g_off[t + 1] = sh[t];
        g_cur[t] = sh[t] - dv;
        if (t == 0) g_off[0] = 0;
    }
}
__global__ void csr_fill(const int* __restrict__ ei) {
    int e = blockIdx.x * blockDim.x + threadIdx.x;
    if (e >= NE) return;
    int s, d; edge_sd(e, ei, s, d);
    int pos = atomicAdd(&g_cur[d], 1);
    g_srcv[pos] = s;
}

// ---------------- 3. precompute w_as = W @ a_src / a_dst (all 5 layers) ----------------
__global__ void prep_was(const float* __restrict__ W,
                         const float* __restrict__ a_s,
                         const float* __restrict__ a_d) {
    int l = blockIdx.x / 12;
    int kt = blockIdx.x % 12;
    int t = threadIdx.x;
    int k = kt * 64 + (t & 63);
    int sp = t >> 6;
    const float* wseg = W + (size_t)l * DD * DD + (size_t)k * DD + sp * DHH;
    const float* av = a_s + l * DD + sp * DHH;
    const float* bv = a_d + l * DD + sp * DHH;
    float s0 = 0.f, s1 = 0.f;
#pragma unroll 8
    for (int i = 0; i < DHH; i += 4) {
        float4 w = *(const float4*)&wseg[i];
        float4 a = *(const float4*)&av[i];
        float4 b = *(const float4*)&bv[i];
        s0 += w.x * a.x + w.y * a.y + w.z * a.z + w.w * a.w;
        s1 += w.x * b.x + w.y * b.y + w.z * b.z + w.w * b.w;
    }
    g_was[(l * 8 + sp) * DD + k]     = s0;
    g_was[(l * 8 + sp + 4) * DD + k] = s1;
}

// ---------------- 4. tf32 tensor-core GEMM g_h = g_x @ W, alpha sidecar on bn==0 ----------------
__global__ __launch_bounds__(256) void gemm_xw(const float* __restrict__ Wl,
                                               const float* __restrict__ wasl) {
    __shared__ __align__(16) float As[2][64][AP];
    __shared__ __align__(16) float Bs[2][32][BP];
    __shared__ __align__(16) float Ws[2][8][32];
    int tid = threadIdx.x;
    int bm = blockIdx.y * 64, bn = blockIdx.x * 64;
    bool side = (blockIdx.x == 0);
    int wid = tid >> 5, lane = tid & 31;
    int wm = wid >> 2, wn = wid & 3;
    int g = lane >> 2, tig = lane & 3;
    int lrow = lane & 15;
    int lkoff = (lane < 16) ? 0 : 4;

    float d[2][2][4];
#pragma unroll
    for (int i = 0; i < 2; i++)
#pragma unroll
        for (int j = 0; j < 2; j++)
#pragma unroll
            for (int q = 0; q < 4; q++) d[i][j][q] = 0.f;

    float sa0 = 0.f, sa1 = 0.f;
    int sr = tid & 63, sp = tid >> 6;

    int am1 = tid >> 3, aq = tid & 7;
    int bk1 = tid >> 4, bq = tid & 15;
    int wslot = tid >> 3, wq = tid & 7;

    uint32_t as_base = (uint32_t)__cvta_generic_to_shared(&As[0][0][0]);
    uint32_t bs_base = (uint32_t)__cvta_generic_to_shared(&Bs[0][0][0]);
    uint32_t ws_base = (uint32_t)__cvta_generic_to_shared(&Ws[0][0][0]);

#define LOAD_TILE(buf, k0)                                                              \
    do {                                                                                \
        cpa16(as_base + ((buf) * 64 * AP + am1 * AP + aq * 4) * 4,                      \
              &g_x[(bm + am1) * DD + (k0) + aq * 4]);                                   \
        cpa16(as_base + ((buf) * 64 * AP + (am1 + 32) * AP + aq * 4) * 4,               \
              &g_x[(bm + am1 + 32) * DD + (k0) + aq * 4]);                              \
        cpa16(bs_base + ((buf) * 32 * BP + bk1 * BP + bq * 4) * 4,                      \
              &Wl[(size_t)((k0) + bk1) * DD + bn + bq * 4]);                            \
        cpa16(bs_base + ((buf) * 32 * BP + (bk1 + 16) * BP + bq * 4) * 4,               \
              &Wl[(size_t)((k0) + bk1 + 16) * DD + bn + bq * 4]);                       \
        if (side && tid < 64)                                                           \
            cpa16(ws_base + ((buf) * 8 * 32 + wslot * 32 + wq * 4) * 4,                 \
                  &wasl[wslot * DD + (k0) + wq * 4]);                                   \
        cpa_commit();                                                                   \
    } while (0)

    LOAD_TILE(0, 0);

#pragma unroll 1
    for (int t = 0; t < KTILES; t++) {
        if (t + 1 < KTILES) {
            LOAD_TILE((t + 1) & 1, (t + 1) * 32);
            asm volatile("cp.async.wait_group 1;\n");
        } else {
            asm volatile("cp.async.wait_group 0;\n");
        }
        __syncthreads();
        int buf = t & 1;
        // A fragment base for ldmatrix: row = wm*32 + lrow, col = lkoff
        uint32_t abase = as_base + (buf * 64 * AP + (wm * 32 + lrow) * AP + lkoff) * 4;
#pragma unroll
        for (int ks = 0; ks < 4; ks++) {
            int kk = ks * 8;
            uint32_t a[2][4], b[2][2];
#pragma unroll
            for (int mt = 0; mt < 2; mt++) {
                uint32_t addr = abase + mt * (16 * AP * 4) + ks * 32;
                asm volatile(
                    "ldmatrix.sync.aligned.m8n8.x4.shared.b16 {%0,%1,%2,%3}, [%4];\n"
                    : "=r"(a[mt][0]), "=r"(a[mt][1]), "=r"(a[mt][2]), "=r"(a[mt][3])
                    : "r"(addr));
            }
#pragma unroll
            for (int nt = 0; nt < 2; nt++) {
                int c0 = wn * 16 + nt * 8 + g;
                b[nt][0] = __float_as_uint(Bs[buf][kk + tig][c0]);
                b[nt][1] = __float_as_uint(Bs[buf][kk + tig + 4][c0]);
            }
#pragma unroll
            for (int mt = 0; mt < 2; mt++)
#pragma unroll
                for (int nt = 0; nt < 2; nt++) {
                    asm volatile(
                        "mma.sync.aligned.m16n8k8.row.col.f32.tf32.tf32.f32 "
                        "{%0,%1,%2,%3}, {%4,%5,%6,%7}, {%8,%9}, {%0,%1,%2,%3};\n"
                        : "+f"(d[mt][nt][0]), "+f"(d[mt][nt][1]),
                          "+f"(d[mt][nt][2]), "+f"(d[mt][nt][3])
                        : "r"(a[mt][0]), "r"(a[mt][1]), "r"(a[mt][2]), "r"(a[mt][3]),
                          "r"(b[nt][0]), "r"(b[nt][1]));
                }
        }
        if (side) {
#pragma unroll
            for (int q = 0; q < 8; q++) {
                float4 xv = *(const float4*)&As[buf][sr][q * 4];
                float4 w0 = *(const float4*)&Ws[buf][sp][q * 4];
                float4 w1 = *(const float4*)&Ws[buf][sp + 4][q * 4];
                sa0 += xv.x * w0.x + xv.y * w0.y + xv.z * w0.z + xv.w * w0.w;
                sa1 += xv.x * w1.x + xv.y * w1.y + xv.z * w1.z + xv.w * w1.w;
            }
        }
        __syncthreads();
    }

#pragma unroll
    for (int mt = 0; mt < 2; mt++)
#pragma unroll
        for (int nt = 0; nt < 2; nt++) {
            int row = bm + wm * 32 + mt * 16 + g;
            int col = bn + wn * 16 + nt * 8 + 2 * tig;
            *(float2*)&g_h[(size_t)row * DD + col] =
                make_float2(d[mt][nt][0], d[mt][nt][1]);
            *(float2*)&g_h[(size_t)(row + 8) * DD + col] =
                make_float2(d[mt][nt][2], d[mt][nt][3]);
        }
    if (side) {
        int r = bm + sr;
        g_as[r * HH + sp] = sa0;
        g_ad[r * HH + sp] = sa1;
    }
#undef LOAD_TILE
}

// ---------------- 5. online-softmax aggregate + bias + GELU (single pass) ----------------
__global__ void aggregate_gelu(const float* __restrict__ bias) {
    int d = blockIdx.x;
    int t = threadIdx.x;          // 192
    int beg = g_off[d], end = g_off[d + 1];
    int j0 = 4 * t;
    int h = t / 48;
    float ah = g_ad[d * HH + h];
    float m = -3.0e38f, den = 0.f;
    float4 acc = make_float4(0.f, 0.f, 0.f, 0.f);
#pragma unroll 2
    for (int e = beg; e < end; e++) {
        int s = g_srcv[e];
        float lg = g_as[s * HH + h] + ah;
        lg = (lg > 0.f) ? lg : 0.2f * lg;
        float nm = fmaxf(m, lg);
        float sc = __expf(m - nm);
        float p  = __expf(lg - nm);
        float4 hv = *(const float4*)&g_h[(size_t)s * DD + j0];
        den = den * sc + p;
        acc.x = acc.x * sc + p * hv.x;
        acc.y = acc.y * sc + p * hv.y;
        acc.z = acc.z * sc + p * hv.z;
        acc.w = acc.w * sc + p * hv.w;
        m = nm;
    }
    float inv = 1.0f / den;
    float4 b4 = *(const float4*)&bias[j0];
    float o0 = acc.x * inv + b4.x;
    float o1 = acc.y * inv + b4.y;
    float o2 = acc.z * inv + b4.z;
    float o3 = acc.w * inv + b4.w;
    float4 r;
    r.x = 0.5f * o0 * (1.0f + erff(o0 * 0.70710678118654752f));
    r.y = 0.5f * o1 * (1.0f + erff(o1 * 0.70710678118654752f));
    r.z = 0.5f * o2 * (1.0f + erff(o2 * 0.70710678118654752f));
    r.w = 0.5f * o3 * (1.0f + erff(o3 * 0.70710678118654752f));
    *(float4*)&g_x[(size_t)d * DD + j0] = r;
}

// ---------------- 6. final embedding sum + LayerNorm ----------------
__global__ __launch_bounds__(256) void final_ln(
                         const int* __restrict__ src, const int* __restrict__ seg,
                         const int* __restrict__ typ, const int* __restrict__ pos,
                         const float* __restrict__ wt, const float* __restrict__ pt,
                         const float* __restrict__ st, const float* __restrict__ tt,
                         const float* __restrict__ gamma, const float* __restrict__ beta,
                         float* __restrict__ out) {
    int row = blockIdx.x * 8 + (threadIdx.x >> 5);
    int lane = threadIdx.x & 31;
    int b = row / SS, s = row % SS;
    const float* wrow = (s == 0) ? &g_x[(size_t)(b * NPER) * DD]
                                 : &wt[(size_t)src[row] * DD];
    const float* prow = &pt[(size_t)pos[row] * DD];
    const float* srow = &st[(size_t)seg[row] * DD];
    const float* trow = &tt[(size_t)typ[row] * DD];
    float4 v[6];
    float sum = 0.0f, sq = 0.0f;
#pragma unroll
    for (int i = 0; i < 6; i++) {
        int f = (lane + i * 32) * 4;
        float4 w = *(const float4*)&wrow[f];
        float4 p = *(const float4*)&prow[f];
        float4 sg = *(const float4*)&srow[f];
        float4 ty = *(const float4*)&trow[f];
        float4 e = make_float4(w.x + p.x + sg.x + ty.x, w.y + p.y + sg.y + ty.y,
                               w.z + p.z + sg.z + ty.z, w.w + p.w + sg.w + ty.w);
        v[i] = e;
        sum += e.x + e.y + e.z + e.w;
        sq += e.x * e.x + e.y * e.y + e.z * e.z + e.w * e.w;
    }
#pragma unroll
    for (int o = 16; o; o >>= 1) {
        sum += __shfl_xor_sync(0xffffffffu, sum, o);
        sq  += __shfl_xor_sync(0xffffffffu, sq, o);
    }
    float mu  = sum * (1.0f / DD);
    float var = sq * (1.0f / DD) - mu * mu;
    float inv = rsqrtf(var + 1e-6f);
#pragma unroll
    for (int i = 0; i < 6; i++) {
        int f = (lane + i * 32) * 4;
        float4 g4 = *(const float4*)&gamma[f];
        float4 b4 = *(const float4*)&beta[f];
        float4 r;
        r.x = g4.x * (v[i].x - mu) * inv + b4.x;
        r.y = g4.y * (v[i].y - mu) * inv + b4.y;
        r.z = g4.z * (v[i].z - mu) * inv + b4.z;
        r.w = g4.w * (v[i].w - mu) * inv + b4.w;
        __stcs((float4*)&out[(size_t)row * DD + f], r);   // streaming store: keep L2 for gathers
    }
}

extern "C" void kernel_launch(void* const* d_in, const int* in_sizes, int n_in,
                              void* d_out, int out_size) {
    const int*   src        = (const int*)d_in[0];
    const int*   seg        = (const int*)d_in[1];
    const int*   type_ids   = (const int*)d_in[2];
    const int*   pos        = (const int*)d_in[3];
    const int*   span_start = (const int*)d_in[4];
    const int*   span_end   = (const int*)d_in[5];
    const int*   edge_idx   = (const int*)d_in[6];
    const float* word_table = (const float*)d_in[7];
    const float* pos_table  = (const float*)d_in[8];
    const float* seg_table  = (const float*)d_in[9];
    const float* type_table = (const float*)d_in[10];
    const float* gamma      = (const float*)d_in[11];
    const float* beta       = (const float*)d_in[12];
    const float* W_gat      = (const float*)d_in[13];
    const float* a_src      = (const float*)d_in[14];
    const float* a_dst      = (const float*)d_in[15];
    const float* b_gat      = (const float*)d_in[16];
    float* out = (float*)d_out;

    build_nodes<<<NN, 192>>>(src, span_start, span_end, word_table);
    csr_count<<<(NE + 255) / 256, 256>>>(edge_idx);
    csr_scan<<<1, 1024>>>();
    csr_fill<<<(NE + 255) / 256, 256>>>(edge_idx);
    prep_was<<<60, 256>>>(W_gat, a_src, a_dst);

    float* was_dev;
    cudaGetSymbolAddress((void**)&was_dev, g_was);

    for (int l = 0; l < 5; l++) {
        gemm_xw<<<dim3(12, 9), 256>>>(W_gat + (size_t)l * DD * DD,
                                      was_dev + (size_t)l * 8 * DD);
        aggregate_gelu<<<NN, 192>>>(b_gat + l * DD);
    }

    final_ln<<<(BB * SS) / 8, 256>>>(src, seg, type_ids, pos,
                                     word_table, pos_table, seg_table, type_table,
                                     gamma, beta, out);
}

// round 12
// speedup vs baseline: 1.2265x; 1.0093x over previous
#include <cuda_runtime.h>
#include <math.h>
#include <stdint.h>

#define BB 64
#define SS 512
#define DD 768
#define HH 4
#define DHH 192
#define PP 8
#define NPER 9
#define NN 576
#define E0 4096
#define NE 8768       // 2*E0 + NN self loops
#define KTILES 24     // 768 / 32

// GEMM dynamic smem layout (bytes), 3 stages:
//  As: 3 * 64 * 36 * 4 = 27648  (row stride 144 B)
//  Bs: 3 * 32 * 72 * 4 = 27648  (base 27648, row stride 288 B)
//  Ws: 3 * 8 * 32 * 4  =  3072  (base 55296)
#define SMEM_BYTES 58368
#define A_OFF(s,m,q4) ((s)*9216 + (m)*144 + (q4)*16)
#define B_OFF(s,k,q4) (27648 + (s)*9216 + (k)*288 + (q4)*16)
#define W_OFF(s,p,q4) (55296 + (s)*1024 + (p)*128 + (q4)*16)

// ---------------- device scratch ----------------
__device__ float g_x[NN * DD];
__device__ float g_h[NN * DD];
__device__ float g_as[NN * HH];
__device__ float g_ad[NN * HH];
__device__ float g_was[5 * 8 * DD];     // per layer: 0-3 = W@a_src heads, 4-7 = W@a_dst
__device__ int   g_off[NN + 1];
__device__ int   g_srcv[NE];

__device__ __forceinline__ void edge_sd(int e, const int* __restrict__ ei, int& s, int& d) {
    if (e < E0)          { s = ei[e];      d = ei[E0 + e]; }
    else if (e < 2 * E0) { s = ei[e];      d = ei[e - E0]; }
    else                 { s = e - 2 * E0; d = e - 2 * E0; }
}

__device__ __forceinline__ void cpa16(uint32_t saddr, const void* gptr) {
    asm volatile("cp.async.cg.shared.global [%0], [%1], 16;\n" :: "r"(saddr), "l"(gptr));
}
__device__ __forceinline__ void cpa_commit() { asm volatile("cp.async.commit_group;\n"); }

// =========== 1. fused setup: nodes + prep_was + in-smem CSR build ===========
__global__ __launch_bounds__(256) void setup_all(
    const int* __restrict__ src,
    const int* __restrict__ sstart,
    const int* __restrict__ send,
    const int* __restrict__ ei,
    const float* __restrict__ wt,
    const float* __restrict__ W,
    const float* __restrict__ a_s,
    const float* __restrict__ a_d)
{
    __shared__ int s_int[576 + 256 + 576 + 576];   // sdeg | part | vals | scur
    const int bid = blockIdx.x;
    const int tid = threadIdx.x;

    if (bid < NN) {
        // ---- build node ----
        if (tid < 192) {
            int node = bid;
            int b = node / NPER, p = node % NPER;
            int j0 = 4 * tid;
            float4 v = make_float4(0.f, 0.f, 0.f, 0.f);
            if (p == 0) {
                v = *(const float4*)&wt[(size_t)src[b * SS] * DD + j0];
            } else {
                int st = sstart[b * PP + (p - 1)];
                int en = send[b * PP + (p - 1)];
                for (int s = st; s <= en; s++) {
                    float4 w = *(const float4*)&wt[(size_t)src[b * SS + s] * DD + j0];
                    v.x += w.x; v.y += w.y; v.z += w.z; v.w += w.w;
                }
            }
            *(float4*)&g_x[node * DD + j0] = v;
        }
    } else if (bid < NN + 60) {
        // ---- prep_was: w_as = W @ a_src / a_dst ----
        int bid2 = bid - NN;
        int l = bid2 / 12, kt = bid2 % 12;
        int k = kt * 64 + (tid & 63);
        int sp = tid >> 6;
        const float* wseg = W + (size_t)l * DD * DD + (size_t)k * DD + sp * DHH;
        const float* av = a_s + l * DD + sp * DHH;
        const float* bv = a_d + l * DD + sp * DHH;
        float s0 = 0.f, s1 = 0.f;
#pragma unroll 8
        for (int i = 0; i < DHH; i += 4) {
            float4 w = *(const float4*)&wseg[i];
            float4 a = *(const float4*)&av[i];
            float4 b = *(const float4*)&bv[i];
            s0 += w.x * a.x + w.y * a.y + w.z * a.z + w.w * a.w;
            s1 += w.x * b.x + w.y * b.y + w.z * b.z + w.w * b.w;
        }
        g_was[(l * 8 + sp) * DD + k]     = s0;
        g_was[(l * 8 + sp + 4) * DD + k] = s1;
    } else {
        // ---- single-block CSR build, entirely in shared memory ----
        int* sdeg = s_int;
        int* part = s_int + 576;
        int* vals = part + 256;
        int* scur = vals + 576;
        for (int i = tid; i < NN; i += 256) sdeg[i] = 0;
        __syncthreads();
        for (int e = tid; e < NE; e += 256) {
            int s, d; edge_sd(e, ei, s, d);
            atomicAdd(&sdeg[d], 1);
        }
        __syncthreads();
        if (tid < 192) {
            int s = 0;
#pragma unroll
            for (int j = 0; j < 3; j++) {
                int v = sdeg[tid * 3 + j];
                vals[tid * 3 + j] = v; s += v;
            }
            part[tid] = s;
        }
        __syncthreads();
        for (int off = 1; off < 192; off <<= 1) {
            int v = (tid < 192 && tid >= off) ? part[tid - off] : 0;
            __syncthreads();
            if (tid < 192) part[tid] += v;
            __syncthreads();
        }
        if (tid < 192) {
            int run = part[tid] - (vals[tid * 3] + vals[tid * 3 + 1] + vals[tid * 3 + 2]);
#pragma unroll
            for (int j = 0; j < 3; j++) {
                g_off[tid * 3 + j] = run;
                scur[tid * 3 + j] = run;
                run += vals[tid * 3 + j];
            }
            if (tid == 191) g_off[NN] = run;
        }
        __syncthreads();
        for (int e = tid; e < NE; e += 256) {
            int s, d; edge_sd(e, ei, s, d);
            int pos = atomicAdd(&scur[d], 1);
            g_srcv[pos] = s;
        }
    }
}

// === 2. tf32 tensor-core GEMM g_h = g_x @ W (3-stage pipeline, alpha sidecar) ===
__global__ __launch_bounds__(256) void gemm_xw(const float* __restrict__ Wl,
                                               const float* __restrict__ wasl) {
    extern __shared__ __align__(16) char smem_raw[];
    float* smf = (float*)smem_raw;
    uint32_t smem_base = (uint32_t)__cvta_generic_to_shared(smem_raw);

    int tid = threadIdx.x;
    int bm = blockIdx.y * 64, bn = blockIdx.x * 64;
    bool side = (blockIdx.x == 0);
    int wid = tid >> 5, lane = tid & 31;
    int wm = wid >> 2, wn = wid & 3;
    int g = lane >> 2, tig = lane & 3;
    int lrow = lane & 15;
    int lkoff = (lane < 16) ? 0 : 4;

    float d[2][2][4];
#pragma unroll
    for (int i = 0; i < 2; i++)
#pragma unroll
        for (int j = 0; j < 2; j++)
#pragma unroll
            for (int q = 0; q < 4; q++) d[i][j][q] = 0.f;

    float sa0 = 0.f, sa1 = 0.f;
    int sr = tid & 63, sp = tid >> 6;

    int am1 = tid >> 3, aq = tid & 7;
    int bk1 = tid >> 4, bq = tid & 15;
    int wslot = tid >> 3, wq = tid & 7;

#define LOAD_TILE(st, k0)                                                                  \
    do {                                                                                   \
        cpa16(smem_base + A_OFF(st, am1, aq),      &g_x[(bm + am1) * DD + (k0) + aq * 4]); \
        cpa16(smem_base + A_OFF(st, am1 + 32, aq), &g_x[(bm + am1 + 32) * DD + (k0) + aq * 4]); \
        cpa16(smem_base + B_OFF(st, bk1, bq),      &Wl[(size_t)((k0) + bk1) * DD + bn + bq * 4]); \
        cpa16(smem_base + B_OFF(st, bk1 + 16, bq), &Wl[(size_t)((k0) + bk1 + 16) * DD + bn + bq * 4]); \
        if (side && tid < 64)                                                              \
            cpa16(smem_base + W_OFF(st, wslot, wq), &wasl[wslot * DD + (k0) + wq * 4]);    \
        cpa_commit();                                                                      \
    } while (0)

    LOAD_TILE(0, 0);
    LOAD_TILE(1, 32);

#pragma unroll 1
    for (int t = 0; t < KTILES; t++) {
        if (t < KTILES - 1) asm volatile("cp.async.wait_group 1;\n");
        else                asm volatile("cp.async.wait_group 0;\n");
        __syncthreads();
        if (t + 2 < KTILES) {
            int st2 = (t + 2) % 3;
            LOAD_TILE(st2, (t + 2) * 32);
        }
        const int st3 = t % 3;
        uint32_t abase = smem_base + st3 * 9216 + (wm * 32 + lrow) * 144 + lkoff * 4;
#pragma unroll
        for (int ks = 0; ks < 4; ks++) {
            int kk = ks * 8;
            uint32_t a[2][4], b[2][2];
#pragma unroll
            for (int mt = 0; mt < 2; mt++) {
                uint32_t addr = abase + mt * (16 * 144) + ks * 32;
                asm volatile(
                    "ldmatrix.sync.aligned.m8n8.x4.shared.b16 {%0,%1,%2,%3}, [%4];\n"
                    : "=r"(a[mt][0]), "=r"(a[mt][1]), "=r"(a[mt][2]), "=r"(a[mt][3])
                    : "r"(addr));
            }
#pragma unroll
            for (int nt = 0; nt < 2; nt++) {
                int c0 = wn * 16 + nt * 8 + g;
                b[nt][0] = __float_as_uint(smf[6912 + st3 * 2304 + (kk + tig) * 72 + c0]);
                b[nt][1] = __float_as_uint(smf[6912 + st3 * 2304 + (kk + tig + 4) * 72 + c0]);
            }
#pragma unroll
            for (int mt = 0; mt < 2; mt++)
#pragma unroll
                for (int nt = 0; nt < 2; nt++) {
                    asm volatile(
                        "mma.sync.aligned.m16n8k8.row.col.f32.tf32.tf32.f32 "
                        "{%0,%1,%2,%3}, {%4,%5,%6,%7}, {%8,%9}, {%0,%1,%2,%3};\n"
                        : "+f"(d[mt][nt][0]), "+f"(d[mt][nt][1]),
                          "+f"(d[mt][nt][2]), "+f"(d[mt][nt][3])
                        : "r"(a[mt][0]), "r"(a[mt][1]), "r"(a[mt][2]), "r"(a[mt][3]),
                          "r"(b[nt][0]), "r"(b[nt][1]));
                }
        }
        if (side) {
#pragma unroll
            for (int q = 0; q < 8; q++) {
                float4 xv = *(const float4*)(smem_raw + A_OFF(st3, sr, q));
                float4 w0 = *(const float4*)(smem_raw + W_OFF(st3, sp, q));
                float4 w1 = *(const float4*)(smem_raw + W_OFF(st3, sp + 4, q));
                sa0 += xv.x * w0.x + xv.y * w0.y + xv.z * w0.z + xv.w * w0.w;
                sa1 += xv.x * w1.x + xv.y * w1.y + xv.z * w1.z + xv.w * w1.w;
            }
        }
    }
#undef LOAD_TILE

#pragma unroll
    for (int mt = 0; mt < 2; mt++)
#pragma unroll
        for (int nt = 0; nt < 2; nt++) {
            int row = bm + wm * 32 + mt * 16 + g;
            int col = bn + wn * 16 + nt * 8 + 2 * tig;
            *(float2*)&g_h[(size_t)row * DD + col] =
                make_float2(d[mt][nt][0], d[mt][nt][1]);
            *(float2*)&g_h[(size_t)(row + 8) * DD + col] =
                make_float2(d[mt][nt][2], d[mt][nt][3]);
        }
    if (side) {
        int r = bm + sr;
        g_as[r * HH + sp] = sa0;
        g_ad[r * HH + sp] = sa1;
    }
}

// ------- 3. online-softmax aggregate + bias + GELU (single pass) -------
__global__ void aggregate_gelu(const float* __restrict__ bias) {
    int d = blockIdx.x;
    int t = threadIdx.x;          // 192
    int beg = g_off[d], end = g_off[d + 1];
    int j0 = 4 * t;
    int h = t / 48;
    float ah = g_ad[d * HH + h];
    float m = -3.0e38f, den = 0.f;
    float4 acc = make_float4(0.f, 0.f, 0.f, 0.f);
#pragma unroll 2
    for (int e = beg; e < end; e++) {
        int s = g_srcv[e];
        float lg = g_as[s * HH + h] + ah;
        lg = (lg > 0.f) ? lg : 0.2f * lg;
        float nm = fmaxf(m, lg);
        float sc = __expf(m - nm);
        float p  = __expf(lg - nm);
        float4 hv = *(const float4*)&g_h[(size_t)s * DD + j0];
        den = den * sc + p;
        acc.x = acc.x * sc + p * hv.x;
        acc.y = acc.y * sc + p * hv.y;
        acc.z = acc.z * sc + p * hv.z;
        acc.w = acc.w * sc + p * hv.w;
        m = nm;
    }
    float inv = 1.0f / den;
    float4 b4 = *(const float4*)&bias[j0];
    float o0 = acc.x * inv + b4.x;
    float o1 = acc.y * inv + b4.y;
    float o2 = acc.z * inv + b4.z;
    float o3 = acc.w * inv + b4.w;
    float4 r;
    r.x = 0.5f * o0 * (1.0f + erff(o0 * 0.70710678118654752f));
    r.y = 0.5f * o1 * (1.0f + erff(o1 * 0.70710678118654752f));
    r.z = 0.5f * o2 * (1.0f + erff(o2 * 0.70710678118654752f));
    r.w = 0.5f * o3 * (1.0f + erff(o3 * 0.70710678118654752f));
    *(float4*)&g_x[(size_t)d * DD + j0] = r;
}

// ------- 4. final embedding sum + LayerNorm -------
__global__ __launch_bounds__(256) void final_ln(
                         const int* __restrict__ src, const int* __restrict__ seg,
                         const int* __restrict__ typ, const int* __restrict__ pos,
                         const float* __restrict__ wt, const float* __restrict__ pt,
                         const float* __restrict__ st, const float* __restrict__ tt,
                         const float* __restrict__ gamma, const float* __restrict__ beta,
                         float* __restrict__ out) {
    int row = blockIdx.x * 8 + (threadIdx.x >> 5);
    int lane = threadIdx.x & 31;
    int b = row / SS, s = row % SS;
    const float* wrow = (s == 0) ? &g_x[(size_t)(b * NPER) * DD]
                                 : &wt[(size_t)src[row] * DD];
    const float* prow = &pt[(size_t)pos[row] * DD];
    const float* srow = &st[(size_t)seg[row] * DD];
    const float* trow = &tt[(size_t)typ[row] * DD];
    float4 v[6];
    float sum = 0.0f, sq = 0.0f;
#pragma unroll
    for (int i = 0; i < 6; i++) {
        int f = (lane + i * 32) * 4;
        float4 w = *(const float4*)&wrow[f];
        float4 p = *(const float4*)&prow[f];
        float4 sg = *(const float4*)&srow[f];
        float4 ty = *(const float4*)&trow[f];
        float4 e = make_float4(w.x + p.x + sg.x + ty.x, w.y + p.y + sg.y + ty.y,
                               w.z + p.z + sg.z + ty.z, w.w + p.w + sg.w + ty.w);
        v[i] = e;
        sum += e.x + e.y + e.z + e.w;
        sq += e.x * e.x + e.y * e.y + e.z * e.z + e.w * e.w;
    }
#pragma unroll
    for (int o = 16; o; o >>= 1) {
        sum += __shfl_xor_sync(0xffffffffu, sum, o);
        sq  += __shfl_xor_sync(0xffffffffu, sq, o);
    }
    float mu  = sum * (1.0f / DD);
    float var = sq * (1.0f / DD) - mu * mu;
    float inv = rsqrtf(var + 1e-6f);
#pragma unroll
    for (int i = 0; i < 6; i++) {
        int f = (lane + i * 32) * 4;
        float4 g4 = *(const float4*)&gamma[f];
        float4 b4 = *(const float4*)&beta[f];
        float4 r;
        r.x = g4.x * (v[i].x - mu) * inv + b4.x;
        r.y = g4.y * (v[i].y - mu) * inv + b4.y;
        r.z = g4.z * (v[i].z - mu) * inv + b4.z;
        r.w = g4.w * (v[i].w - mu) * inv + b4.w;
        __stcs((float4*)&out[(size_t)row * DD + f], r);   // streaming store: keep L2 for gathers
    }
}

extern "C" void kernel_launch(void* const* d_in, const int* in_sizes, int n_in,
                              void* d_out, int out_size) {
    const int*   src        = (const int*)d_in[0];
    const int*   seg        = (const int*)d_in[1];
    const int*   type_ids   = (const int*)d_in[2];
    const int*   pos        = (const int*)d_in[3];
    const int*   span_start = (const int*)d_in[4];
    const int*   span_end   = (const int*)d_in[5];
    const int*   edge_idx   = (const int*)d_in[6];
    const float* word_table = (const float*)d_in[7];
    const float* pos_table  = (const float*)d_in[8];
    const float* seg_table  = (const float*)d_in[9];
    const float* type_table = (const float*)d_in[10];
    const float* gamma      = (const float*)d_in[11];
    const float* beta       = (const float*)d_in[12];
    const float* W_gat      = (const float*)d_in[13];
    const float* a_src      = (const float*)d_in[14];
    const float* a_dst      = (const float*)d_in[15];
    const float* b_gat      = (const float*)d_in[16];
    float* out = (float*)d_out;

    cudaFuncSetAttribute(gemm_xw, cudaFuncAttributeMaxDynamicSharedMemorySize, SMEM_BYTES);

    setup_all<<<NN + 60 + 1, 256>>>(src, span_start, span_end, edge_idx,
                                    word_table, W_gat, a_src, a_dst);

    float* was_dev;
    cudaGetSymbolAddress((void**)&was_dev, g_was);

    for (int l = 0; l < 5; l++) {
        gemm_xw<<<dim3(12, 9), 256, SMEM_BYTES>>>(W_gat + (size_t)l * DD * DD,
                                                  was_dev + (size_t)l * 8 * DD);
        aggregate_gelu<<<NN, 192>>>(b_gat + l * DD);
    }

    final_ln<<<(BB * SS) / 8, 256>>>(src, seg, type_ids, pos,
                                     word_table, pos_table, seg_table, type_table,
                                     gamma, beta, out);
}

// round 14
// speedup vs baseline: 1.2795x; 1.0432x over previous
#include <cuda_runtime.h>
#include <math.h>
#include <stdint.h>

#define BB 64
#define SS 512
#define DD 768
#define HH 4
#define DHH 192
#define PP 8
#define NPER 9
#define NN 576
#define E0 4096
#define NE 8768       // 2*E0 + NN self loops
#define KT_WG 12      // k-tiles per warpgroup (each 32 wide; WG0: 0..383, WG1: 384..767)

// GEMM dynamic smem (bytes):
//  per WG: 3 stages * (A 64x36x4 = 9216 + B 32x72x4 = 9216) = 55296   -> WG base = wg*55296
//  Ws:  110592 + wg*3072 + stage*1024  (8 slots x 32 floats per stage)
//  alpha partial buffer: 116736 (512 floats = 2048 B)
//  WG1 accum dump: reuses WG1 stage0 A region (float idx 13824), valid after WG1 pipeline done
#define SMEM_BYTES 118784

// ---------------- device scratch ----------------
__device__ float g_x[NN * DD];
__device__ float g_h[NN * DD];
__device__ float g_as[NN * HH];
__device__ float g_ad[NN * HH];
__device__ float g_was[5 * 8 * DD];     // per layer: 0-3 = W@a_src heads, 4-7 = W@a_dst
__device__ int   g_off[NN + 1];
__device__ int   g_srcv[NE];

__device__ __forceinline__ void edge_sd(int e, const int* __restrict__ ei, int& s, int& d) {
    if (e < E0)          { s = ei[e];      d = ei[E0 + e]; }
    else if (e < 2 * E0) { s = ei[e];      d = ei[e - E0]; }
    else                 { s = e - 2 * E0; d = e - 2 * E0; }
}

__device__ __forceinline__ void cpa16(uint32_t saddr, const void* gptr) {
    asm volatile("cp.async.cg.shared.global [%0], [%1], 16;\n" :: "r"(saddr), "l"(gptr));
}
__device__ __forceinline__ void cpa_commit() { asm volatile("cp.async.commit_group;\n"); }

// =========== 1. fused setup: nodes + prep_was + in-smem CSR build ===========
__global__ __launch_bounds__(256) void setup_all(
    const int* __restrict__ src,
    const int* __restrict__ sstart,
    const int* __restrict__ send,
    const int* __restrict__ ei,
    const float* __restrict__ wt,
    const float* __restrict__ W,
    const float* __restrict__ a_s,
    const float* __restrict__ a_d)
{
    __shared__ int s_int[576 + 256 + 576 + 576];   // sdeg | part | vals | scur
    const int bid = blockIdx.x;
    const int tid = threadIdx.x;

    if (bid < NN) {
        if (tid < 192) {
            int node = bid;
            int b = node / NPER, p = node % NPER;
            int j0 = 4 * tid;
            float4 v = make_float4(0.f, 0.f, 0.f, 0.f);
            if (p == 0) {
                v = *(const float4*)&wt[(size_t)src[b * SS] * DD + j0];
            } else {
                int st = sstart[b * PP + (p - 1)];
                int en = send[b * PP + (p - 1)];
                for (int s = st; s <= en; s++) {
                    float4 w = *(const float4*)&wt[(size_t)src[b * SS + s] * DD + j0];
                    v.x += w.x; v.y += w.y; v.z += w.z; v.w += w.w;
                }
            }
            *(float4*)&g_x[node * DD + j0] = v;
        }
    } else if (bid < NN + 60) {
        int bid2 = bid - NN;
        int l = bid2 / 12, kt = bid2 % 12;
        int k = kt * 64 + (tid & 63);
        int sp = tid >> 6;
        const float* wseg = W + (size_t)l * DD * DD + (size_t)k * DD + sp * DHH;
        const float* av = a_s + l * DD + sp * DHH;
        const float* bv = a_d + l * DD + sp * DHH;
        float s0 = 0.f, s1 = 0.f;
#pragma unroll 8
        for (int i = 0; i < DHH; i += 4) {
            float4 w = *(const float4*)&wseg[i];
            float4 a = *(const float4*)&av[i];
            float4 b = *(const float4*)&bv[i];
            s0 += w.x * a.x + w.y * a.y + w.z * a.z + w.w * a.w;
            s1 += w.x * b.x + w.y * b.y + w.z * b.z + w.w * b.w;
        }
        g_was[(l * 8 + sp) * DD + k]     = s0;
        g_was[(l * 8 + sp + 4) * DD + k] = s1;
    } else {
        int* sdeg = s_int;
        int* part = s_int + 576;
        int* vals = part + 256;
        int* scur = vals + 576;
        for (int i = tid; i < NN; i += 256) sdeg[i] = 0;
        __syncthreads();
        for (int e = tid; e < NE; e += 256) {
            int s, d; edge_sd(e, ei, s, d);
            atomicAdd(&sdeg[d], 1);
        }
        __syncthreads();
        if (tid < 192) {
            int s = 0;
#pragma unroll
            for (int j = 0; j < 3; j++) {
                int v = sdeg[tid * 3 + j];
                vals[tid * 3 + j] = v; s += v;
            }
            part[tid] = s;
        }
        __syncthreads();
        for (int off = 1; off < 192; off <<= 1) {
            int v = (tid < 192 && tid >= off) ? part[tid - off] : 0;
            __syncthreads();
            if (tid < 192) part[tid] += v;
            __syncthreads();
        }
        if (tid < 192) {
            int run = part[tid] - (vals[tid * 3] + vals[tid * 3 + 1] + vals[tid * 3 + 2]);
#pragma unroll
            for (int j = 0; j < 3; j++) {
                g_off[tid * 3 + j] = run;
                scur[tid * 3 + j] = run;
                run += vals[tid * 3 + j];
            }
            if (tid == 191) g_off[NN] = run;
        }
        __syncthreads();
        for (int e = tid; e < NE; e += 256) {
            int s, d; edge_sd(e, ei, s, d);
            int pos = atomicAdd(&scur[d], 1);
            g_srcv[pos] = s;
        }
    }
}

// === 2. tf32 GEMM g_h = g_x @ W: 512 threads, intra-CTA split-K (2 warpgroups) ===
__global__ __launch_bounds__(512) void gemm_xw(const float* __restrict__ Wl,
                                               const float* __restrict__ wasl) {
    extern __shared__ __align__(16) char smem_raw[];
    float* smf = (float*)smem_raw;
    uint32_t smem_base = (uint32_t)__cvta_generic_to_shared(smem_raw);

    const int tid = threadIdx.x;
    const int wg = tid >> 8;            // warpgroup 0/1
    const int wt = tid & 255;           // tid within warpgroup
    const int bm = blockIdx.y * 64, bn = blockIdx.x * 64;
    const bool side = (blockIdx.x == 0);
    const int kbase = wg * (KT_WG * 32);   // 0 or 384

    const int wid = wt >> 5, lane = tid & 31;
    const int wm = wid >> 2, wn = wid & 3;
    const int g = lane >> 2, tig = lane & 3;
    const int lrow = lane & 15;
    const int lkoff = (lane < 16) ? 0 : 4;

    // smem base addresses for this WG
    const uint32_t wg_base  = smem_base + wg * 55296;
    const int      wg_bfidx = wg * 13824;              // float index of WG B area base
    const uint32_t ws_base  = smem_base + 110592 + wg * 3072;

    float d[2][2][4];
#pragma unroll
    for (int i = 0; i < 2; i++)
#pragma unroll
        for (int j = 0; j < 2; j++)
#pragma unroll
            for (int q = 0; q < 4; q++) d[i][j][q] = 0.f;

    float sa0 = 0.f, sa1 = 0.f;
    const int sr = wt & 63, sp = wt >> 6;

    const int am1 = wt >> 3, aq = wt & 7;
    const int bk1 = wt >> 4, bq = wt & 15;
    const int wslot = wt >> 3, wq = wt & 7;

#define WGBAR() asm volatile("bar.sync %0, 256;\n" :: "r"(wg + 1))

#define LOAD_TILE(st, k0)                                                                       \
    do {                                                                                        \
        cpa16(wg_base + (st) * 18432 + am1 * 144 + aq * 16,                                     \
              &g_x[(bm + am1) * DD + (k0) + aq * 4]);                                           \
        cpa16(wg_base + (st) * 18432 + (am1 + 32) * 144 + aq * 16,                              \
              &g_x[(bm + am1 + 32) * DD + (k0) + aq * 4]);                                      \
        cpa16(wg_base + (st) * 18432 + 9216 + bk1 * 288 + bq * 16,                              \
              &Wl[(size_t)((k0) + bk1) * DD + bn + bq * 4]);                                    \
        cpa16(wg_base + (st) * 18432 + 9216 + (bk1 + 16) * 288 + bq * 16,                       \
              &Wl[(size_t)((k0) + bk1 + 16) * DD + bn + bq * 4]);                               \
        if (side && wt < 64)                                                                    \
            cpa16(ws_base + (st) * 1024 + wslot * 128 + wq * 16,                                \
                  &wasl[wslot * DD + (k0) + wq * 4]);                                           \
        cpa_commit();                                                                           \
    } while (0)

    LOAD_TILE(0, kbase);
    LOAD_TILE(1, kbase + 32);

#pragma unroll 1
    for (int t = 0; t < KT_WG; t++) {
        if (t < KT_WG - 1) asm volatile("cp.async.wait_group 1;\n");
        else               asm volatile("cp.async.wait_group 0;\n");
        WGBAR();
        if (t + 2 < KT_WG) {
            int st2 = (t + 2) % 3;
            LOAD_TILE(st2, kbase + (t + 2) * 32);
        }
        const int st3 = t % 3;
        uint32_t abase = wg_base + st3 * 18432 + (wm * 32 + lrow) * 144 + lkoff * 4;
        const int bfb = wg_bfidx + st3 * 4608 + 2304;
#pragma unroll
        for (int ks = 0; ks < 4; ks++) {
            int kk = ks * 8;
            uint32_t a[2][4], b[2][2];
#pragma unroll
            for (int mt = 0; mt < 2; mt++) {
                uint32_t addr = abase + mt * (16 * 144) + ks * 32;
                asm volatile(
                    "ldmatrix.sync.aligned.m8n8.x4.shared.b16 {%0,%1,%2,%3}, [%4];\n"
                    : "=r"(a[mt][0]), "=r"(a[mt][1]), "=r"(a[mt][2]), "=r"(a[mt][3])
                    : "r"(addr));
            }
#pragma unroll
            for (int nt = 0; nt < 2; nt++) {
                int c0 = wn * 16 + nt * 8 + g;
                b[nt][0] = __float_as_uint(smf[bfb + (kk + tig) * 72 + c0]);
                b[nt][1] = __float_as_uint(smf[bfb + (kk + tig + 4) * 72 + c0]);
            }
#pragma unroll
            for (int mt = 0; mt < 2; mt++)
#pragma unroll
                for (int nt = 0; nt < 2; nt++) {
                    asm volatile(
                        "mma.sync.aligned.m16n8k8.row.col.f32.tf32.tf32.f32 "
                        "{%0,%1,%2,%3}, {%4,%5,%6,%7}, {%8,%9}, {%0,%1,%2,%3};\n"
                        : "+f"(d[mt][nt][0]), "+f"(d[mt][nt][1]),
                          "+f"(d[mt][nt][2]), "+f"(d[mt][nt][3])
                        : "r"(a[mt][0]), "r"(a[mt][1]), "r"(a[mt][2]), "r"(a[mt][3]),
                          "r"(b[nt][0]), "r"(b[nt][1]));
                }
        }
        if (side) {
#pragma unroll
            for (int q = 0; q < 8; q++) {
                float4 xv = *(const float4*)(smem_raw + wg * 55296 + st3 * 18432 + sr * 144 + q * 16);
                float4 w0 = *(const float4*)(smem_raw + 110592 + wg * 3072 + st3 * 1024 + sp * 128 + q * 16);
                float4 w1 = *(const float4*)(smem_raw + 110592 + wg * 3072 + st3 * 1024 + (sp + 4) * 128 + q * 16);
                sa0 += xv.x * w0.x + xv.y * w0.y + xv.z * w0.z + xv.w * w0.w;
                sa1 += xv.x * w1.x + xv.y * w1.y + xv.z * w1.z + xv.w * w1.w;
            }
        }
    }
#undef LOAD_TILE

    // ---- combine the two warpgroups' partial results ----
    float* dump  = smf + 13824;        // WG1 stage0 A region (free now)
    float* abuf  = smf + 29184;        // alpha partial buffer (512 floats)
    if (wg == 1) {
        int base = wt * 16;
#pragma unroll
        for (int mt = 0; mt < 2; mt++)
#pragma unroll
            for (int nt = 0; nt < 2; nt++) {
                dump[base + (mt * 2 + nt) * 4 + 0] = d[mt][nt][0];
                dump[base + (mt * 2 + nt) * 4 + 1] = d[mt][nt][1];
                dump[base + (mt * 2 + nt) * 4 + 2] = d[mt][nt][2];
                dump[base + (mt * 2 + nt) * 4 + 3] = d[mt][nt][3];
            }
        if (side) { abuf[wt * 2] = sa0; abuf[wt * 2 + 1] = sa1; }
    }
    __syncthreads();
    if (wg == 0) {
        int base = wt * 16;
#pragma unroll
        for (int mt = 0; mt < 2; mt++)
#pragma unroll
            for (int nt = 0; nt < 2; nt++) {
                d[mt][nt][0] += dump[base + (mt * 2 + nt) * 4 + 0];
                d[mt][nt][1] += dump[base + (mt * 2 + nt) * 4 + 1];
                d[mt][nt][2] += dump[base + (mt * 2 + nt) * 4 + 2];
                d[mt][nt][3] += dump[base + (mt * 2 + nt) * 4 + 3];
            }
#pragma unroll
        for (int mt = 0; mt < 2; mt++)
#pragma unroll
            for (int nt = 0; nt < 2; nt++) {
                int row = bm + wm * 32 + mt * 16 + g;
                int col = bn + wn * 16 + nt * 8 + 2 * tig;
                *(float2*)&g_h[(size_t)row * DD + col] =
                    make_float2(d[mt][nt][0], d[mt][nt][1]);
                *(float2*)&g_h[(size_t)(row + 8) * DD + col] =
                    make_float2(d[mt][nt][2], d[mt][nt][3]);
            }
        if (side) {
            int r = bm + sr;
            g_as[r * HH + sp] = sa0 + abuf[wt * 2];
            g_ad[r * HH + sp] = sa1 + abuf[wt * 2 + 1];
        }
    }
#undef WGBAR
}

// ------- 3. online-softmax aggregate + bias + GELU (2 independent states) -------
__global__ void aggregate_gelu(const float* __restrict__ bias) {
    int d = blockIdx.x;
    int t = threadIdx.x;          // 192
    int beg = g_off[d], end = g_off[d + 1];
    int j0 = 4 * t;
    int h = t / 48;
    float ah = g_ad[d * HH + h];

    float mA = -3.0e38f, dnA = 0.f;
    float4 aA = make_float4(0.f, 0.f, 0.f, 0.f);
    float mB = -3.0e38f, dnB = 0.f;
    float4 aB = make_float4(0.f, 0.f, 0.f, 0.f);

    int e = beg;
    for (; e + 1 < end; e += 2) {
        int s0 = g_srcv[e], s1 = g_srcv[e + 1];
        float l0 = g_as[s0 * HH + h] + ah; l0 = (l0 > 0.f) ? l0 : 0.2f * l0;
        float l1 = g_as[s1 * HH + h] + ah; l1 = (l1 > 0.f) ? l1 : 0.2f * l1;
        float4 h0 = *(const float4*)&g_h[(size_t)s0 * DD + j0];
        float4 h1 = *(const float4*)&g_h[(size_t)s1 * DD + j0];
        {
            float nm = fmaxf(mA, l0);
            float sc = __expf(mA - nm), p = __expf(l0 - nm);
            dnA = dnA * sc + p;
            aA.x = aA.x * sc + p * h0.x; aA.y = aA.y * sc + p * h0.y;
            aA.z = aA.z * sc + p * h0.z; aA.w = aA.w * sc + p * h0.w;
            mA = nm;
        }
        {
            float nm = fmaxf(mB, l1);
            float sc = __expf(mB - nm), p = __expf(l1 - nm);
            dnB = dnB * sc + p;
            aB.x = aB.x * sc + p * h1.x; aB.y = aB.y * sc + p * h1.y;
            aB.z = aB.z * sc + p * h1.z; aB.w = aB.w * sc + p * h1.w;
            mB = nm;
        }
    }
    if (e < end) {
        int s0 = g_srcv[e];
        float l0 = g_as[s0 * HH + h] + ah; l0 = (l0 > 0.f) ? l0 : 0.2f * l0;
        float4 h0 = *(const float4*)&g_h[(size_t)s0 * DD + j0];
        float nm = fmaxf(mA, l0);
        float sc = __expf(mA - nm), p = __expf(l0 - nm);
        dnA = dnA * sc + p;
        aA.x = aA.x * sc + p * h0.x; aA.y = aA.y * sc + p * h0.y;
        aA.z = aA.z * sc + p * h0.z; aA.w = aA.w * sc + p * h0.w;
        mA = nm;
    }
    // merge state B into A
    float nm = fmaxf(mA, mB);
    float sA = __expf(mA - nm), sB = __expf(mB - nm);
    float den = dnA * sA + dnB * sB;
    float4 acc = make_float4(aA.x * sA + aB.x * sB, aA.y * sA + aB.y * sB,
                             aA.z * sA + aB.z * sB, aA.w * sA + aB.w * sB);

    float inv = 1.0f / den;
    float4 b4 = *(const float4*)&bias[j0];
    float o0 = acc.x * inv + b4.x;
    float o1 = acc.y * inv + b4.y;
    float o2 = acc.z * inv + b4.z;
    float o3 = acc.w * inv + b4.w;
    float4 r;
    r.x = 0.5f * o0 * (1.0f + erff(o0 * 0.70710678118654752f));
    r.y = 0.5f * o1 * (1.0f + erff(o1 * 0.70710678118654752f));
    r.z = 0.5f * o2 * (1.0f + erff(o2 * 0.70710678118654752f));
    r.w = 0.5f * o3 * (1.0f + erff(o3 * 0.70710678118654752f));
    *(float4*)&g_x[(size_t)d * DD + j0] = r;
}

// ------- 4. final embedding sum + LayerNorm -------
__global__ __launch_bounds__(256) void final_ln(
                         const int* __restrict__ src, const int* __restrict__ seg,
                         const int* __restrict__ typ, const int* __restrict__ pos,
                         const float* __restrict__ wt, const float* __restrict__ pt,
                         const float* __restrict__ st, const float* __restrict__ tt,
                         const float* __restrict__ gamma, const float* __restrict__ beta,
                         float* __restrict__ out) {
    int row = blockIdx.x * 8 + (threadIdx.x >> 5);
    int lane = threadIdx.x & 31;
    int b = row / SS, s = row % SS;
    const float* wrow = (s == 0) ? &g_x[(size_t)(b * NPER) * DD]
                                 : &wt[(size_t)src[row] * DD];
    const float* prow = &pt[(size_t)pos[row] * DD];
    const float* srow = &st[(size_t)seg[row] * DD];
    const float* trow = &tt[(size_t)typ[row] * DD];
    float4 v[6];
    float sum = 0.0f, sq = 0.0f;
#pragma unroll
    for (int i = 0; i < 6; i++) {
        int f = (lane + i * 32) * 4;
        float4 w = *(const float4*)&wrow[f];
        float4 p = *(const float4*)&prow[f];
        float4 sg = *(const float4*)&srow[f];
        float4 ty = *(const float4*)&trow[f];
        float4 e = make_float4(w.x + p.x + sg.x + ty.x, w.y + p.y + sg.y + ty.y,
                               w.z + p.z + sg.z + ty.z, w.w + p.w + sg.w + ty.w);
        v[i] = e;
        sum += e.x + e.y + e.z + e.w;
        sq += e.x * e.x + e.y * e.y + e.z * e.z + e.w * e.w;
    }
#pragma unroll
    for (int o = 16; o; o >>= 1) {
        sum += __shfl_xor_sync(0xffffffffu, sum, o);
        sq  += __shfl_xor_sync(0xffffffffu, sq, o);
    }
    float mu  = sum * (1.0f / DD);
    float var = sq * (1.0f / DD) - mu * mu;
    float inv = rsqrtf(var + 1e-6f);
#pragma unroll
    for (int i = 0; i < 6; i++) {
        int f = (lane + i * 32) * 4;
        float4 g4 = *(const float4*)&gamma[f];
        float4 b4 = *(const float4*)&beta[f];
        float4 r;
        r.x = g4.x * (v[i].x - mu) * inv + b4.x;
        r.y = g4.y * (v[i].y - mu) * inv + b4.y;
        r.z = g4.z * (v[i].z - mu) * inv + b4.z;
        r.w = g4.w * (v[i].w - mu) * inv + b4.w;
        __stcs((float4*)&out[(size_t)row * DD + f], r);
    }
}

extern "C" void kernel_launch(void* const* d_in, const int* in_sizes, int n_in,
                              void* d_out, int out_size) {
    const int*   src        = (const int*)d_in[0];
    const int*   seg        = (const int*)d_in[1];
    const int*   type_ids   = (const int*)d_in[2];
    const int*   pos        = (const int*)d_in[3];
    const int*   span_start = (const int*)d_in[4];
    const int*   span_end   = (const int*)d_in[5];
    const int*   edge_idx   = (const int*)d_in[6];
    const float* word_table = (const float*)d_in[7];
    const float* pos_table  = (const float*)d_in[8];
    const float* seg_table  = (const float*)d_in[9];
    const float* type_table = (const float*)d_in[10];
    const float* gamma      = (const float*)d_in[11];
    const float* beta       = (const float*)d_in[12];
    const float* W_gat      = (const float*)d_in[13];
    const float* a_src      = (const float*)d_in[14];
    const float* a_dst      = (const float*)d_in[15];
    const float* b_gat      = (const float*)d_in[16];
    float* out = (float*)d_out;

    cudaFuncSetAttribute(gemm_xw, cudaFuncAttributeMaxDynamicSharedMemorySize, SMEM_BYTES);

    setup_all<<<NN + 60 + 1, 256>>>(src, span_start, span_end, edge_idx,
                                    word_table, W_gat, a_src, a_dst);

    float* was_dev;
    cudaGetSymbolAddress((void**)&was_dev, g_was);

    for (int l = 0; l < 5; l++) {
        gemm_xw<<<dim3(12, 9), 512, SMEM_BYTES>>>(W_gat + (size_t)l * DD * DD,
                                                  was_dev + (size_t)l * 8 * DD);
        aggregate_gelu<<<NN, 192>>>(b_gat + l * DD);
    }

    final_ln<<<(BB * SS) / 8, 256>>>(src, seg, type_ids, pos,
                                     word_table, pos_table, seg_table, type_table,
                                     gamma, beta, out);
}

// round 15
// speedup vs baseline: 1.5940x; 1.2458x over previous
#include <cuda_runtime.h>
#include <cuda_bf16.h>
#include <math.h>
#include <stdint.h>

#define BB 64
#define SS 512
#define DD 768
#define HH 4
#define DHH 192
#define PP 8
#define NPER 9
#define NN 576
#define E0 4096
#define NE 8768       // 2*E0 + NN self loops
#define KT_WG 6       // 64-wide k-tiles per warpgroup (WG0: k 0..383, WG1: 384..767)

// GEMM dynamic smem (bytes):
//  per WG stage: A 64x144 = 9216  +  B 64x144 = 9216  -> 18432; 3 stages; WG base = wg*55296
//  Ws (fp32): 110592 + wg*6144 + st*2048   (8 slots x 64 floats)
//  alpha partials: 122880 (512 floats)
//  WG1 dump: reuses WG1 stage0 (byte 55296, 18432 B >= 16 KB)
#define SMEM_BYTES 124928

// ---------------- device scratch ----------------
__device__ float g_x[NN * DD];                    // fp32 x (aggregate output; final_ln reads CLS rows)
__device__ __nv_bfloat16 g_xb[NN * DD];           // bf16 x (GEMM A operand)
__device__ __nv_bfloat16 g_wb[5 * DD * DD];       // bf16 W, TRANSPOSED: [l][n][k]
__device__ float g_h[NN * DD];
__device__ float g_as[NN * HH];
__device__ float g_ad[NN * HH];
__device__ float g_was[5 * 8 * DD];               // per layer: 0-3 = W@a_src heads, 4-7 = W@a_dst
__device__ int   g_off[NN + 1];
__device__ int   g_srcv[NE];

__device__ __forceinline__ void edge_sd(int e, const int* __restrict__ ei, int& s, int& d) {
    if (e < E0)          { s = ei[e];      d = ei[E0 + e]; }
    else if (e < 2 * E0) { s = ei[e];      d = ei[e - E0]; }
    else                 { s = e - 2 * E0; d = e - 2 * E0; }
}

__device__ __forceinline__ void cpa16(uint32_t saddr, const void* gptr) {
    asm volatile("cp.async.cg.shared.global [%0], [%1], 16;\n" :: "r"(saddr), "l"(gptr));
}
__device__ __forceinline__ void cpa_commit() { asm volatile("cp.async.commit_group;\n"); }

// === 1. fused setup: nodes(bf16) + prep_was + CSR + W transpose/convert ===
// grid: [0,576) nodes | [576,636) prep_was | 636 CSR | [637,1357) W transpose 64x64 tiles
__global__ __launch_bounds__(256) void setup_all(
    const int* __restrict__ src,
    const int* __restrict__ sstart,
    const int* __restrict__ send,
    const int* __restrict__ ei,
    const float* __restrict__ wt,
    const float* __restrict__ W,
    const float* __restrict__ a_s,
    const float* __restrict__ a_d)
{
    __shared__ __align__(16) char s_buf[64 * 65 * 4];   // 16640 B, aliased per branch
    const int bid = blockIdx.x;
    const int tid = threadIdx.x;

    if (bid < NN) {
        if (tid < 192) {
            int node = bid;
            int b = node / NPER, p = node % NPER;
            int j0 = 4 * tid;
            float4 v = make_float4(0.f, 0.f, 0.f, 0.f);
            if (p == 0) {
                v = *(const float4*)&wt[(size_t)src[b * SS] * DD + j0];
            } else {
                int st = sstart[b * PP + (p - 1)];
                int en = send[b * PP + (p - 1)];
                for (int s = st; s <= en; s++) {
                    float4 w = *(const float4*)&wt[(size_t)src[b * SS + s] * DD + j0];
                    v.x += w.x; v.y += w.y; v.z += w.z; v.w += w.w;
                }
            }
            __nv_bfloat162* dst = (__nv_bfloat162*)&g_xb[node * DD + j0];
            dst[0] = __floats2bfloat162_rn(v.x, v.y);
            dst[1] = __floats2bfloat162_rn(v.z, v.w);
        }
    } else if (bid < NN + 60) {
        int bid2 = bid - NN;
        int l = bid2 / 12, kt = bid2 % 12;
        int k = kt * 64 + (tid & 63);
        int sp = tid >> 6;
        const float* wseg = W + (size_t)l * DD * DD + (size_t)k * DD + sp * DHH;
        const float* av = a_s + l * DD + sp * DHH;
        const float* bv = a_d + l * DD + sp * DHH;
        float s0 = 0.f, s1 = 0.f;
#pragma unroll 8
        for (int i = 0; i < DHH; i += 4) {
            float4 w = *(const float4*)&wseg[i];
            float4 a = *(const float4*)&av[i];
            float4 b = *(const float4*)&bv[i];
            s0 += w.x * a.x + w.y * a.y + w.z * a.z + w.w * a.w;
            s1 += w.x * b.x + w.y * b.y + w.z * b.z + w.w * b.w;
        }
        g_was[(l * 8 + sp) * DD + k]     = s0;
        g_was[(l * 8 + sp + 4) * DD + k] = s1;
    } else if (bid == NN + 60) {
        int* sdeg = (int*)s_buf;
        int* part = sdeg + 576;
        int* vals = part + 256;
        int* scur = vals + 576;
        for (int i = tid; i < NN; i += 256) sdeg[i] = 0;
        __syncthreads();
        for (int e = tid; e < NE; e += 256) {
            int s, d; edge_sd(e, ei, s, d);
            atomicAdd(&sdeg[d], 1);
        }
        __syncthreads();
        if (tid < 192) {
            int s = 0;
#pragma unroll
            for (int j = 0; j < 3; j++) {
                int v = sdeg[tid * 3 + j];
                vals[tid * 3 + j] = v; s += v;
            }
            part[tid] = s;
        }
        __syncthreads();
        for (int off = 1; off < 192; off <<= 1) {
            int v = (tid < 192 && tid >= off) ? part[tid - off] : 0;
            __syncthreads();
            if (tid < 192) part[tid] += v;
            __syncthreads();
        }
        if (tid < 192) {
            int run = part[tid] - (vals[tid * 3] + vals[tid * 3 + 1] + vals[tid * 3 + 2]);
#pragma unroll
            for (int j = 0; j < 3; j++) {
                g_off[tid * 3 + j] = run;
                scur[tid * 3 + j] = run;
                run += vals[tid * 3 + j];
            }
            if (tid == 191) g_off[NN] = run;
        }
        __syncthreads();
        for (int e = tid; e < NE; e += 256) {
            int s, d; edge_sd(e, ei, s, d);
            int pos = atomicAdd(&scur[d], 1);
            g_srcv[pos] = s;
        }
    } else {
        // ---- W transpose+convert: wb[l][n][k] = bf16(W[l][k][n]), 64x64 tile ----
        float* Tr = (float*)s_buf;          // [64][65]
        int tix = bid - (NN + 61);
        int l = tix / 144;
        int rem = tix % 144;
        int k0 = (rem / 12) * 64;
        int n0 = (rem % 12) * 64;
        const float* Wl = W + (size_t)l * DD * DD;
        int c = tid & 63;
        int r0 = tid >> 6;                  // 0..3
#pragma unroll
        for (int i = 0; i < 16; i++) {
            int r = r0 + i * 4;
            Tr[r * 65 + c] = Wl[(size_t)(k0 + r) * DD + n0 + c];
        }
        __syncthreads();
        int nloc = tid >> 2;                // 0..63
        int kq = tid & 3;
        __nv_bfloat16* wb = g_wb + (size_t)l * DD * DD + (size_t)(n0 + nloc) * DD + k0 + kq * 16;
#pragma unroll
        for (int j = 0; j < 16; j += 2) {
            int k = kq * 16 + j;
            *(__nv_bfloat162*)&wb[j] = __floats2bfloat162_rn(Tr[k * 65 + nloc],
                                                             Tr[(k + 1) * 65 + nloc]);
        }
    }
}

// === 2. bf16 GEMM g_h = x @ W: 512 threads, intra-CTA split-K, m16n8k16 ===
__global__ __launch_bounds__(512) void gemm_xw(const __nv_bfloat16* __restrict__ Wlb,
                                               const float* __restrict__ wasl) {
    extern __shared__ __align__(16) char smem_raw[];
    float* smf = (float*)smem_raw;
    uint32_t smem_base = (uint32_t)__cvta_generic_to_shared(smem_raw);

    const int tid = threadIdx.x;
    const int wg = tid >> 8;
    const int wt = tid & 255;
    const int bm = blockIdx.y * 64, bn = blockIdx.x * 64;
    const bool side = (blockIdx.x == 0);
    const int kbase = wg * (KT_WG * 64);   // 0 or 384

    const int wid = wt >> 5, lane = tid & 31;
    const int wm = wid >> 2, wn = wid & 3;
    const int g = lane >> 2, tig = lane & 3;
    const int lrow = lane & 15;
    const int lkoff = (lane >> 4) << 4;    // 0 / 16 bytes

    const uint32_t wg_base = smem_base + wg * 55296;
    const uint32_t ws_base = smem_base + 110592 + wg * 6144;

    float d[2][2][4];
#pragma unroll
    for (int i = 0; i < 2; i++)
#pragma unroll
        for (int j = 0; j < 2; j++)
#pragma unroll
            for (int q = 0; q < 4; q++) d[i][j][q] = 0.f;

    float sa0 = 0.f, sa1 = 0.f;
    const int sr = wt & 63, sp = wt >> 6;

    const int am1 = wt >> 3, aq = wt & 7;      // row 0..31(+32), 16B chunk 0..7

#define WGBAR() asm volatile("bar.sync %0, 256;\n" :: "r"(wg + 1))

#define LOAD_TILE(st, k0)                                                                    \
    do {                                                                                     \
        cpa16(wg_base + (st) * 18432 + am1 * 144 + aq * 16,                                  \
              &g_xb[(bm + am1) * DD + (k0) + aq * 8]);                                       \
        cpa16(wg_base + (st) * 18432 + (am1 + 32) * 144 + aq * 16,                           \
              &g_xb[(bm + am1 + 32) * DD + (k0) + aq * 8]);                                  \
        cpa16(wg_base + (st) * 18432 + 9216 + am1 * 144 + aq * 16,                           \
              &Wlb[(size_t)(bn + am1) * DD + (k0) + aq * 8]);                                \
        cpa16(wg_base + (st) * 18432 + 9216 + (am1 + 32) * 144 + aq * 16,                    \
              &Wlb[(size_t)(bn + am1 + 32) * DD + (k0) + aq * 8]);                           \
        if (side && wt < 128)                                                                \
            cpa16(ws_base + (st) * 2048 + (wt >> 4) * 256 + (wt & 15) * 16,                  \
                  &wasl[(wt >> 4) * DD + (k0) + (wt & 15) * 4]);                             \
        cpa_commit();                                                                        \
    } while (0)

    LOAD_TILE(0, kbase);
    LOAD_TILE(1, kbase + 64);

#pragma unroll 1
    for (int t = 0; t < KT_WG; t++) {
        if (t < KT_WG - 1) asm volatile("cp.async.wait_group 1;\n");
        else               asm volatile("cp.async.wait_group 0;\n");
        WGBAR();
        if (t + 2 < KT_WG) {
            int st2 = (t + 2) % 3;
            LOAD_TILE(st2, kbase + (t + 2) * 64);
        }
        const int st3 = t % 3;
        uint32_t abase = wg_base + st3 * 18432 + (wm * 32 + lrow) * 144 + lkoff;
        const char* braw = smem_raw + wg * 55296 + st3 * 18432 + 9216;
#pragma unroll
        for (int ks = 0; ks < 4; ks++) {      // 4 x k16 per 64-wide tile
            uint32_t a[2][4], b[2][2];
#pragma unroll
            for (int mt = 0; mt < 2; mt++) {
                uint32_t addr = abase + mt * (16 * 144) + ks * 32;
                asm volatile(
                    "ldmatrix.sync.aligned.m8n8.x4.shared.b16 {%0,%1,%2,%3}, [%4];\n"
                    : "=r"(a[mt][0]), "=r"(a[mt][1]), "=r"(a[mt][2]), "=r"(a[mt][3])
                    : "r"(addr));
            }
#pragma unroll
            for (int nt = 0; nt < 2; nt++) {
                int c0 = wn * 16 + nt * 8 + g;
                const char* bp = braw + c0 * 144 + ks * 32 + tig * 4;
                b[nt][0] = *(const uint32_t*)bp;
                b[nt][1] = *(const uint32_t*)(bp + 16);
            }
#pragma unroll
            for (int mt = 0; mt < 2; mt++)
#pragma unroll
                for (int nt = 0; nt < 2; nt++) {
                    asm volatile(
                        "mma.sync.aligned.m16n8k16.row.col.f32.bf16.bf16.f32 "
                        "{%0,%1,%2,%3}, {%4,%5,%6,%7}, {%8,%9}, {%0,%1,%2,%3};\n"
                        : "+f"(d[mt][nt][0]), "+f"(d[mt][nt][1]),
                          "+f"(d[mt][nt][2]), "+f"(d[mt][nt][3])
                        : "r"(a[mt][0]), "r"(a[mt][1]), "r"(a[mt][2]), "r"(a[mt][3]),
                          "r"(b[nt][0]), "r"(b[nt][1]));
                }
        }
        if (side) {
            const char* arow = smem_raw + wg * 55296 + st3 * 18432 + sr * 144;
            const float* wsf = (const float*)(smem_raw + 110592 + wg * 6144 + st3 * 2048);
#pragma unroll
            for (int q = 0; q < 16; q++) {
                __nv_bfloat162 u = *(const __nv_bfloat162*)(arow + q * 4);
                float2 xv = __bfloat1622float2(u);
                sa0 += xv.x * wsf[sp * 64 + 2 * q]       + xv.y * wsf[sp * 64 + 2 * q + 1];
                sa1 += xv.x * wsf[(sp + 4) * 64 + 2 * q] + xv.y * wsf[(sp + 4) * 64 + 2 * q + 1];
            }
        }
    }
#undef LOAD_TILE

    // ---- combine the two warpgroups' partials ----
    float* dump = smf + 13824;        // byte 55296: WG1 stage0 (A+B = 18432 B >= 16 KB)
    float* abuf = smf + 30720;        // byte 122880
    if (wg == 1) {
        int base = wt * 16;
#pragma unroll
        for (int mt = 0; mt < 2; mt++)
#pragma unroll
            for (int nt = 0; nt < 2; nt++) {
                dump[base + (mt * 2 + nt) * 4 + 0] = d[mt][nt][0];
                dump[base + (mt * 2 + nt) * 4 + 1] = d[mt][nt][1];
                dump[base + (mt * 2 + nt) * 4 + 2] = d[mt][nt][2];
                dump[base + (mt * 2 + nt) * 4 + 3] = d[mt][nt][3];
            }
        if (side) { abuf[wt * 2] = sa0; abuf[wt * 2 + 1] = sa1; }
    }
    __syncthreads();
    if (wg == 0) {
        int base = wt * 16;
#pragma unroll
        for (int mt = 0; mt < 2; mt++)
#pragma unroll
            for (int nt = 0; nt < 2; nt++) {
                d[mt][nt][0] += dump[base + (mt * 2 + nt) * 4 + 0];
                d[mt][nt][1] += dump[base + (mt * 2 + nt) * 4 + 1];
                d[mt][nt][2] += dump[base + (mt * 2 + nt) * 4 + 2];
                d[mt][nt][3] += dump[base + (mt * 2 + nt) * 4 + 3];
            }
#pragma unroll
        for (int mt = 0; mt < 2; mt++)
#pragma unroll
            for (int nt = 0; nt < 2; nt++) {
                int row = bm + wm * 32 + mt * 16 + g;
                int col = bn + wn * 16 + nt * 8 + 2 * tig;
                *(float2*)&g_h[(size_t)row * DD + col] =
                    make_float2(d[mt][nt][0], d[mt][nt][1]);
                *(float2*)&g_h[(size_t)(row + 8) * DD + col] =
                    make_float2(d[mt][nt][2], d[mt][nt][3]);
            }
        if (side) {
            int r = bm + sr;
            g_as[r * HH + sp] = sa0 + abuf[wt * 2];
            g_ad[r * HH + sp] = sa1 + abuf[wt * 2 + 1];
        }
    }
#undef WGBAR
}

// ------- 3. online-softmax aggregate + bias + GELU (2 states) -------
__global__ void aggregate_gelu(const float* __restrict__ bias) {
    int d = blockIdx.x;
    int t = threadIdx.x;          // 192
    int beg = g_off[d], end = g_off[d + 1];
    int j0 = 4 * t;
    int h = t / 48;
    float ah = g_ad[d * HH + h];

    float mA = -3.0e38f, dnA = 0.f;
    float4 aA = make_float4(0.f, 0.f, 0.f, 0.f);
    float mB = -3.0e38f, dnB = 0.f;
    float4 aB = make_float4(0.f, 0.f, 0.f, 0.f);

    int e = beg;
    for (; e + 1 < end; e += 2) {
        int s0 = g_srcv[e], s1 = g_srcv[e + 1];
        float l0 = g_as[s0 * HH + h] + ah; l0 = (l0 > 0.f) ? l0 : 0.2f * l0;
        float l1 = g_as[s1 * HH + h] + ah; l1 = (l1 > 0.f) ? l1 : 0.2f * l1;
        float4 h0 = *(const float4*)&g_h[(size_t)s0 * DD + j0];
        float4 h1 = *(const float4*)&g_h[(size_t)s1 * DD + j0];
        {
            float nm = fmaxf(mA, l0);
            float sc = __expf(mA - nm), p = __expf(l0 - nm);
            dnA = dnA * sc + p;
            aA.x = aA.x * sc + p * h0.x; aA.y = aA.y * sc + p * h0.y;
            aA.z = aA.z * sc + p * h0.z; aA.w = aA.w * sc + p * h0.w;
            mA = nm;
        }
        {
            float nm = fmaxf(mB, l1);
            float sc = __expf(mB - nm), p = __expf(l1 - nm);
            dnB = dnB * sc + p;
            aB.x = aB.x * sc + p * h1.x; aB.y = aB.y * sc + p * h1.y;
            aB.z = aB.z * sc + p * h1.z; aB.w = aB.w * sc + p * h1.w;
            mB = nm;
        }
    }
    if (e < end) {
        int s0 = g_srcv[e];
        float l0 = g_as[s0 * HH + h] + ah; l0 = (l0 > 0.f) ? l0 : 0.2f * l0;
        float4 h0 = *(const float4*)&g_h[(size_t)s0 * DD + j0];
        float nm = fmaxf(mA, l0);
        float sc = __expf(mA - nm), p = __expf(l0 - nm);
        dnA = dnA * sc + p;
        aA.x = aA.x * sc + p * h0.x; aA.y = aA.y * sc + p * h0.y;
        aA.z = aA.z * sc + p * h0.z; aA.w = aA.w * sc + p * h0.w;
        mA = nm;
    }
    float nm = fmaxf(mA, mB);
    float sA = __expf(mA - nm), sB = __expf(mB - nm);
    float den = dnA * sA + dnB * sB;
    float4 acc = make_float4(aA.x * sA + aB.x * sB, aA.y * sA + aB.y * sB,
                             aA.z * sA + aB.z * sB, aA.w * sA + aB.w * sB);

    float inv = 1.0f / den;
    float4 b4 = *(const float4*)&bias[j0];
    float o0 = acc.x * inv + b4.x;
    float o1 = acc.y * inv + b4.y;
    float o2 = acc.z * inv + b4.z;
    float o3 = acc.w * inv + b4.w;
    float4 r;
    r.x = 0.5f * o0 * (1.0f + erff(o0 * 0.70710678118654752f));
    r.y = 0.5f * o1 * (1.0f + erff(o1 * 0.70710678118654752f));
    r.z = 0.5f * o2 * (1.0f + erff(o2 * 0.70710678118654752f));
    r.w = 0.5f * o3 * (1.0f + erff(o3 * 0.70710678118654752f));
    *(float4*)&g_x[(size_t)d * DD + j0] = r;
    __nv_bfloat162* xb = (__nv_bfloat162*)&g_xb[(size_t)d * DD + j0];
    xb[0] = __floats2bfloat162_rn(r.x, r.y);
    xb[1] = __floats2bfloat162_rn(r.z, r.w);
}

// ------- 4. final embedding sum + LayerNorm -------
__global__ __launch_bounds__(256) void final_ln(
                         const int* __restrict__ src, const int* __restrict__ seg,
                         const int* __restrict__ typ, const int* __restrict__ pos,
                         const float* __restrict__ wt, const float* __restrict__ pt,
                         const float* __restrict__ st, const float* __restrict__ tt,
                         const float* __restrict__ gamma, const float* __restrict__ beta,
                         float* __restrict__ out) {
    int row = blockIdx.x * 8 + (threadIdx.x >> 5);
    int lane = threadIdx.x & 31;
    int b = row / SS, s = row % SS;
    const float* wrow = (s == 0) ? &g_x[(size_t)(b * NPER) * DD]
                                 : &wt[(size_t)src[row] * DD];
    const float* prow = &pt[(size_t)pos[row] * DD];
    const float* srow = &st[(size_t)seg[row] * DD];
    const float* trow = &tt[(size_t)typ[row] * DD];
    float4 v[6];
    float sum = 0.0f, sq = 0.0f;
#pragma unroll
    for (int i = 0; i < 6; i++) {
        int f = (lane + i * 32) * 4;
        float4 w = *(const float4*)&wrow[f];
        float4 p = *(const float4*)&prow[f];
        float4 sg = *(const float4*)&srow[f];
        float4 ty = *(const float4*)&trow[f];
        float4 e = make_float4(w.x + p.x + sg.x + ty.x, w.y + p.y + sg.y + ty.y,
                               w.z + p.z + sg.z + ty.z, w.w + p.w + sg.w + ty.w);
        v[i] = e;
        sum += e.x + e.y + e.z + e.w;
        sq += e.x * e.x + e.y * e.y + e.z * e.z + e.w * e.w;
    }
#pragma unroll
    for (int o = 16; o; o >>= 1) {
        sum += __shfl_xor_sync(0xffffffffu, sum, o);
        sq  += __shfl_xor_sync(0xffffffffu, sq, o);
    }
    float mu  = sum * (1.0f / DD);
    float var = sq * (1.0f / DD) - mu * mu;
    float inv = rsqrtf(var + 1e-6f);
#pragma unroll
    for (int i = 0; i < 6; i++) {
        int f = (lane + i * 32) * 4;
        float4 g4 = *(const float4*)&gamma[f];
        float4 b4 = *(const float4*)&beta[f];
        float4 r;
        r.x = g4.x * (v[i].x - mu) * inv + b4.x;
        r.y = g4.y * (v[i].y - mu) * inv + b4.y;
        r.z = g4.z * (v[i].z - mu) * inv + b4.z;
        r.w = g4.w * (v[i].w - mu) * inv + b4.w;
        __stcs((float4*)&out[(size_t)row * DD + f], r);
    }
}

extern "C" void kernel_launch(void* const* d_in, const int* in_sizes, int n_in,
                              void* d_out, int out_size) {
    const int*   src        = (const int*)d_in[0];
    const int*   seg        = (const int*)d_in[1];
    const int*   type_ids   = (const int*)d_in[2];
    const int*   pos        = (const int*)d_in[3];
    const int*   span_start = (const int*)d_in[4];
    const int*   span_end   = (const int*)d_in[5];
    const int*   edge_idx   = (const int*)d_in[6];
    const float* word_table = (const float*)d_in[7];
    const float* pos_table  = (const float*)d_in[8];
    const float* seg_table  = (const float*)d_in[9];
    const float* type_table = (const float*)d_in[10];
    const float* gamma      = (const float*)d_in[11];
    const float* beta       = (const float*)d_in[12];
    const float* W_gat      = (const float*)d_in[13];
    const float* a_src      = (const float*)d_in[14];
    const float* a_dst      = (const float*)d_in[15];
    const float* b_gat      = (const float*)d_in[16];
    float* out = (float*)d_out;

    cudaFuncSetAttribute(gemm_xw, cudaFuncAttributeMaxDynamicSharedMemorySize, SMEM_BYTES);

    setup_all<<<NN + 60 + 1 + 720, 256>>>(src, span_start, span_end, edge_idx,
                                          word_table, W_gat, a_src, a_dst);

    float* was_dev;
    cudaGetSymbolAddress((void**)&was_dev, g_was);
    __nv_bfloat16* wb_dev;
    cudaGetSymbolAddress((void**)&wb_dev, g_wb);

    for (int l = 0; l < 5; l++) {
        gemm_xw<<<dim3(12, 9), 512, SMEM_BYTES>>>(wb_dev + (size_t)l * DD * DD,
                                                  was_dev + (size_t)l * 8 * DD);
        aggregate_gelu<<<NN, 192>>>(b_gat + l * DD);
    }

    final_ln<<<(BB * SS) / 8, 256>>>(src, seg, type_ids, pos,
                                     word_table, pos_table, seg_table, type_table,
                                     gamma, beta, out);
}